// round 1
// baseline (speedup 1.0000x reference)
#include <cuda_runtime.h>
#include <cuda_bf16.h>

#define NDIM 2048
#define BATCH 8192

// Scratch: 5 buffers of N*N fp32 (16 MB each, 80 MB total) as device globals
// (allocation APIs are forbidden; __device__ globals are the sanctioned path).
__device__ float g_S [NDIM * NDIM];
__device__ float g_S2[NDIM * NDIM];
__device__ float g_S3[NDIM * NDIM];
__device__ float g_A [NDIM * NDIM];   // M2, then Q
__device__ float g_B [NDIM * NDIM];   // M1

// ---------------------------------------------------------------------------
// build_S: scatter strict upper triangle of flat vector, antisymmetrize.
// triu_indices order: row-major over rows, cols ascending.
// offset(r) = r*(N-1) - r*(r-1)/2
// ---------------------------------------------------------------------------
__global__ void build_S_kernel(const float* __restrict__ flat,
                               float* __restrict__ S) {
    int idx = blockIdx.x * blockDim.x + threadIdx.x;
    if (idx >= NDIM * NDIM) return;
    int r = idx / NDIM;
    int c = idx % NDIM;
    float v = 0.0f;
    if (r < c) {
        int off = r * (NDIM - 1) - (r * (r - 1)) / 2;
        v = flat[off + (c - r - 1)];
    } else if (r > c) {
        int off = c * (NDIM - 1) - (c * (c - 1)) / 2;
        v = -flat[off + (r - c - 1)];
    }
    S[idx] = v;
}

// ---------------------------------------------------------------------------
// poly3: C = beta*C + cI*I + cS*S + cS2*S2 + cS3*S3   (elementwise, diag cI)
// ---------------------------------------------------------------------------
__global__ void poly3_kernel(float* __restrict__ C,
                             const float* __restrict__ S,
                             const float* __restrict__ S2,
                             const float* __restrict__ S3,
                             float beta, float cI, float cS, float cS2, float cS3) {
    int idx = blockIdx.x * blockDim.x + threadIdx.x;
    if (idx >= NDIM * NDIM) return;
    int r = idx / NDIM;
    int c = idx % NDIM;
    float v = beta * C[idx] + cS * S[idx] + cS2 * S2[idx] + cS3 * S3[idx];
    if (r == c) v += cI;
    C[idx] = v;
}

// ---------------------------------------------------------------------------
// SGEMM: C[M x Nc] = A[M x K] @ B[K x Nc], all row-major.
// 128x128 block tile, BK=8, 256 threads, 8x8 register microtile.
// Requires M,Nc multiples of 128 and K multiple of 8 (true here: 2048/8192).
// ---------------------------------------------------------------------------
#define BM 128
#define BN 128
#define BK 8
#define TM 8
#define TN 8

__global__ __launch_bounds__(256, 2)
void sgemm_kernel(int M, int Nc, int K,
                  const float* __restrict__ A,
                  const float* __restrict__ B,
                  float* __restrict__ C) {
    __shared__ float As[BK][BM];
    __shared__ float Bs[BK][BN];

    const int tid = threadIdx.x;
    const int tcol = tid % (BN / TN);   // 0..15
    const int trow = tid / (BN / TN);   // 0..15

    // A tile load: BM x BK = 1024 floats = 256 float4, one per thread.
    const int aRow = tid / (BK / 4);        // tid/2: 0..127
    const int aCol = (tid % (BK / 4)) * 4;  // 0 or 4
    // B tile load: BK x BN = 1024 floats = 256 float4, one per thread.
    const int bRow = tid / (BN / 4);        // tid/32: 0..7
    const int bCol = (tid % (BN / 4)) * 4;  // 0..124

    A += (size_t)blockIdx.y * BM * K;
    B += (size_t)blockIdx.x * BN;
    C += (size_t)blockIdx.y * BM * Nc + (size_t)blockIdx.x * BN;

    float acc[TM][TN] = {};
    float regM[TM];
    float regN[TN];

    for (int k0 = 0; k0 < K; k0 += BK) {
        float4 av = *reinterpret_cast<const float4*>(A + (size_t)aRow * K + k0 + aCol);
        As[aCol + 0][aRow] = av.x;
        As[aCol + 1][aRow] = av.y;
        As[aCol + 2][aRow] = av.z;
        As[aCol + 3][aRow] = av.w;
        float4 bv = *reinterpret_cast<const float4*>(B + (size_t)(k0 + bRow) * Nc + bCol);
        *reinterpret_cast<float4*>(&Bs[bRow][bCol]) = bv;
        __syncthreads();

#pragma unroll
        for (int kk = 0; kk < BK; kk++) {
            // vectorized smem reads (LDS.128) to dodge 4-way bank conflicts
            *reinterpret_cast<float4*>(&regM[0]) = *reinterpret_cast<const float4*>(&As[kk][trow * TM]);
            *reinterpret_cast<float4*>(&regM[4]) = *reinterpret_cast<const float4*>(&As[kk][trow * TM + 4]);
            *reinterpret_cast<float4*>(&regN[0]) = *reinterpret_cast<const float4*>(&Bs[kk][tcol * TN]);
            *reinterpret_cast<float4*>(&regN[4]) = *reinterpret_cast<const float4*>(&Bs[kk][tcol * TN + 4]);
#pragma unroll
            for (int i = 0; i < TM; i++)
#pragma unroll
                for (int j = 0; j < TN; j++)
                    acc[i][j] = fmaf(regM[i], regN[j], acc[i][j]);
        }
        __syncthreads();
    }

#pragma unroll
    for (int i = 0; i < TM; i++) {
#pragma unroll
        for (int j = 0; j < TN; j += 4) {
            float4 v;
            v.x = acc[i][j + 0];
            v.y = acc[i][j + 1];
            v.z = acc[i][j + 2];
            v.w = acc[i][j + 3];
            *reinterpret_cast<float4*>(C + (size_t)(trow * TM + i) * Nc + tcol * TN + j) = v;
        }
    }
}

// ---------------------------------------------------------------------------
// Paterson–Stockmeyer evaluation of exp(S) truncated at degree 9:
//   Q = P0 + S3*(P1 + S3*(P2 + (1/9!)*S3)),
//   P0 = I + S + S2/2
//   P1 = I/6 + S/24 + S2/120
//   P2 = I/720 + S/5040 + S2/40320
// Then Y = X @ Q.  5 GEMMs total (4 at 2048^3 + 1 at 8192*2048^2).
// ---------------------------------------------------------------------------
extern "C" void kernel_launch(void* const* d_in, const int* in_sizes, int n_in,
                              void* d_out, int out_size) {
    const float* X    = (const float*)d_in[0];
    const float* flat = (const float*)d_in[1];
    float*       Y    = (float*)d_out;

    float *S, *S2, *S3, *A, *Bbuf;
    cudaGetSymbolAddress((void**)&S,    g_S);
    cudaGetSymbolAddress((void**)&S2,   g_S2);
    cudaGetSymbolAddress((void**)&S3,   g_S3);
    cudaGetSymbolAddress((void**)&A,    g_A);
    cudaGetSymbolAddress((void**)&Bbuf, g_B);

    const int NN = NDIM * NDIM;
    const int EW_THREADS = 256;
    const int EW_BLOCKS = NN / EW_THREADS;

    dim3 g_nn(NDIM / BN, NDIM / BM);          // 16 x 16
    dim3 g_xn(NDIM / BN, BATCH / BM);         // 16 x 64
    dim3 blk(256);

    // 1. S from flat
    build_S_kernel<<<EW_BLOCKS, EW_THREADS>>>(flat, S);

    // 2. S2 = S @ S ; S3 = S2 @ S
    sgemm_kernel<<<g_nn, blk>>>(NDIM, NDIM, NDIM, S, S, S2);
    sgemm_kernel<<<g_nn, blk>>>(NDIM, NDIM, NDIM, S2, S, S3);

    // 3. A = M2 = I/720 + S/5040 + S2/40320 + S3/362880
    poly3_kernel<<<EW_BLOCKS, EW_THREADS>>>(A, S, S2, S3,
        0.0f, 1.0f / 720.0f, 1.0f / 5040.0f, 1.0f / 40320.0f, 1.0f / 362880.0f);

    // 4. B = S3 @ M2 ; B += P1 = I/6 + S/24 + S2/120   -> M1
    sgemm_kernel<<<g_nn, blk>>>(NDIM, NDIM, NDIM, S3, A, Bbuf);
    poly3_kernel<<<EW_BLOCKS, EW_THREADS>>>(Bbuf, S, S2, S3,
        1.0f, 1.0f / 6.0f, 1.0f / 24.0f, 1.0f / 120.0f, 0.0f);

    // 5. A = S3 @ M1 ; A += P0 = I + S + S2/2          -> Q
    sgemm_kernel<<<g_nn, blk>>>(NDIM, NDIM, NDIM, S3, Bbuf, A);
    poly3_kernel<<<EW_BLOCKS, EW_THREADS>>>(A, S, S2, S3,
        1.0f, 1.0f, 1.0f, 0.5f, 0.0f);

    // 6. Y = X @ Q
    sgemm_kernel<<<g_xn, blk>>>(BATCH, NDIM, NDIM, X, A, Y);
}

// round 10
// speedup vs baseline: 4.5029x; 4.5029x over previous
#include <cuda_runtime.h>
#include <cuda_bf16.h>
#include <cstdint>

#define NDIM  2048
#define BATCH 8192
#define K3    (3 * NDIM)        // 6144 (split-K concatenation)
#define CHUNKS (K3 / 64)        // 96 K-chunks of 64 bf16
#define STAGES 3
#define STAGE_BYTES 65536       // A tile 32KB + B tile 32KB
#define SMEM_DYN (STAGES * STAGE_BYTES + 1024)

// tcgen05 is an arch-accelerated ("a") feature: it must be compiled ONLY in
// the sm_103a/sm_100a pass. The harness also runs a plain compute_103 pass,
// which would reject the PTX — stub the kernel body there.
#if defined(__CUDA_ARCH_FEAT_SM103_ALL) || defined(__CUDA_ARCH_FEAT_SM100_ALL)
#define HAS_TCGEN05 1
#else
#define HAS_TCGEN05 0
#endif

// ---------------- device scratch (allocation APIs forbidden) ----------------
__device__ float g_S [NDIM * NDIM];
__device__ float g_S2[NDIM * NDIM];
__device__ float g_S3[NDIM * NDIM];
__device__ float g_P [NDIM * NDIM];   // M2, then Q
__device__ float g_R [NDIM * NDIM];   // M1
__device__ __nv_bfloat16 g_bufA[NDIM  * K3];  // A-split (reused: S, S2, S3)
__device__ __nv_bfloat16 g_SBt [NDIM  * K3];  // Bt-split of S
__device__ __nv_bfloat16 g_WBt [NDIM  * K3];  // Bt-split of M2 / M1 / Q
__device__ __nv_bfloat16 g_XA  [BATCH * K3];  // A-split of X

// ---------------- PTX helpers ----------------
__device__ __forceinline__ uint32_t smem_to_u32(const void* p) {
    uint32_t a;
    asm("{ .reg .u64 t; cvta.to.shared.u64 t, %1; cvt.u32.u64 %0, t; }"
        : "=r"(a) : "l"(p));
    return a;
}
#define SMEM_SWIZZLE_128B(o) ((o) ^ (((o) >> 3) & 0x70))

static constexpr uint64_t SMEM_DESC_BASE_SW128 =
    (uint64_t(2) << 61) | (uint64_t(1) << 46) | (uint64_t(64) << 32) | (uint64_t(1) << 16);
#define MAKE_SMEM_DESC(base) (SMEM_DESC_BASE_SW128 | ((uint64_t)((base) >> 4) & 0x3FFF))

#define MBARRIER_INIT(addr, cnt) \
    asm volatile("mbarrier.init.shared.b64 [%0], %1;" :: "r"((uint32_t)(addr)), "r"((uint32_t)(cnt)) : "memory")

#define MBARRIER_WAIT_PARITY(addr, par) do {                                   \
    uint32_t _m = (uint32_t)(addr); uint32_t _p = (uint32_t)(par); uint32_t _d;\
    asm volatile("{\n\t.reg .pred p;\n\t"                                       \
        "mbarrier.try_wait.parity.acquire.cta.shared::cta.b64 p, [%1], %2;\n\t" \
        "selp.b32 %0, 1, 0, p;\n\t}" : "=r"(_d) : "r"(_m), "r"(_p) : "memory"); \
    if (!_d) {                                                                  \
        asm volatile("{\n\t.reg .pred P1;\n\tWL_%=:\n\t"                        \
            "mbarrier.try_wait.parity.acquire.cta.shared::cta.b64 P1, [%0], %1, 0x989680;\n\t" \
            "@P1 bra.uni WD_%=;\n\tbra.uni WL_%=;\n\tWD_%=:\n\t}"               \
            :: "r"(_m), "r"(_p) : "memory");                                    \
    }                                                                           \
} while (0)

#define CP_ASYNC16(dst, src) \
    asm volatile("cp.async.cg.shared.global [%0], [%1], 16;" :: "r"(dst), "l"(src) : "memory")
#define CP_COMMIT() asm volatile("cp.async.commit_group;" ::: "memory")

#if HAS_TCGEN05
__device__ __forceinline__ uint32_t elect_one_pred() {
    uint32_t p;
    asm volatile("{\n\t.reg .pred p;\n\telect.sync _|p, 0xFFFFFFFF;\n\t"
                 "selp.b32 %0, 1, 0, p;\n\t}" : "=r"(p));
    return p;
}
#define TCGEN05_ALLOC(saddr, n) \
    asm volatile("tcgen05.alloc.cta_group::1.sync.aligned.shared::cta.b32 [%0], %1;" \
                 :: "r"((uint32_t)(saddr)), "r"((uint32_t)(n)) : "memory")
#define TCGEN05_DEALLOC(t, n) \
    asm volatile("tcgen05.dealloc.cta_group::1.sync.aligned.b32 %0, %1;" :: "r"(t), "r"((uint32_t)(n)))
#define TCGEN05_RELINQ() \
    asm volatile("tcgen05.relinquish_alloc_permit.cta_group::1.sync.aligned;")
#define TCGEN05_COMMIT(mb) \
    asm volatile("tcgen05.commit.cta_group::1.mbarrier::arrive::one.shared::cluster.b64 [%0];" \
                 :: "r"((uint32_t)(mb)) : "memory")
#define TCGEN05_FENCE_AFTER() asm volatile("tcgen05.fence::after_thread_sync;" ::: "memory")
#define TCGEN05_FENCE_BEFORE() asm volatile("tcgen05.fence::before_thread_sync;" ::: "memory")
#define TCGEN05_WAIT_LD() asm volatile("tcgen05.wait::ld.sync.aligned;" ::: "memory")

#define TCGEN05_LD_32X32B_X32(r, ta)                                            \
    asm volatile("tcgen05.ld.sync.aligned.32x32b.x32.b32 "                      \
        "{%0, %1, %2, %3, %4, %5, %6, %7, %8, %9, %10, %11, %12, %13, %14, %15,"\
        " %16, %17, %18, %19, %20, %21, %22, %23, %24, %25, %26, %27, %28, %29, %30, %31}, [%32];" \
        : "=r"((r)[0]),  "=r"((r)[1]),  "=r"((r)[2]),  "=r"((r)[3]),            \
          "=r"((r)[4]),  "=r"((r)[5]),  "=r"((r)[6]),  "=r"((r)[7]),            \
          "=r"((r)[8]),  "=r"((r)[9]),  "=r"((r)[10]), "=r"((r)[11]),           \
          "=r"((r)[12]), "=r"((r)[13]), "=r"((r)[14]), "=r"((r)[15]),           \
          "=r"((r)[16]), "=r"((r)[17]), "=r"((r)[18]), "=r"((r)[19]),           \
          "=r"((r)[20]), "=r"((r)[21]), "=r"((r)[22]), "=r"((r)[23]),           \
          "=r"((r)[24]), "=r"((r)[25]), "=r"((r)[26]), "=r"((r)[27]),           \
          "=r"((r)[28]), "=r"((r)[29]), "=r"((r)[30]), "=r"((r)[31])            \
        : "r"(ta))

// idesc: kind::f16, dtype F32, atype/btype BF16, N=256, M=128
static constexpr uint32_t GEMM_IDESC =
    (1u << 4) | (1u << 7) | (1u << 10) | ((256u / 8) << 17) | ((128u / 16) << 24);

__device__ __forceinline__ void mma_f16_ss(uint32_t d, uint64_t a, uint64_t b,
                                           uint32_t idesc, bool acc) {
    uint32_t en = acc ? 1u : 0u;
    asm volatile("{\n\t.reg .pred p;\n\tsetp.ne.u32 p, %5, 0;\n\t"
                 "tcgen05.mma.cta_group::1.kind::f16 [%0], %1, %2, %3, {%4, %4, %4, %4}, p;\n\t}"
                 :: "r"(d), "l"(a), "l"(b), "r"(idesc), "r"(0u), "r"(en) : "memory");
}
#endif  // HAS_TCGEN05

// ---------------------------------------------------------------------------
// bf16 split GEMM: per-CTA C tile 256x256, K' = 6144.
// A  : [Mtot x 6144] row-major bf16 (hi | lo | hi)
// Bt : [2048 x 6144] row-major bf16 (hi | hi | lo)  (B transposed, K-major)
// ---------------------------------------------------------------------------
__device__ __forceinline__ void load_tile(uint32_t stA, uint32_t stB,
                                          const __nv_bfloat16* A, const __nv_bfloat16* Bt,
                                          size_t rowA0, size_t rowB0, int chunk, int tid) {
    const char* gA = (const char*)(A  + rowA0 * K3 + (size_t)chunk * 64);
    const char* gB = (const char*)(Bt + rowB0 * K3 + (size_t)chunk * 64);
#pragma unroll
    for (int i = 0; i < 8; i++) {
        int u = tid + i * 256;              // 0..2047 : 256 rows x 8 x 16B
        int row = u >> 3;
        int o16 = (u & 7) << 4;
        uint32_t dsw = SMEM_SWIZZLE_128B((uint32_t)(row * 128 + o16));
        CP_ASYNC16(stA + dsw, gA + (size_t)row * (K3 * 2) + o16);
        CP_ASYNC16(stB + dsw, gB + (size_t)row * (K3 * 2) + o16);
    }
}

__global__ __launch_bounds__(256, 1)
void gemm_bf16_kernel(const __nv_bfloat16* __restrict__ A,
                      const __nv_bfloat16* __restrict__ Bt,
                      float* __restrict__ C) {
#if HAS_TCGEN05
    extern __shared__ char dyn[];
    __shared__ uint64_t s_mbar[4];        // 0..2 stage-release, 3 done
    __shared__ uint32_t s_tmemptr;

    const int tid = threadIdx.x;
    const int wid = tid >> 5;
    const int lid = tid & 31;
    uint32_t sb = (smem_to_u32(dyn) + 1023) & ~1023u;
    uint32_t mb = smem_to_u32(s_mbar);

    if (tid == 0) {
        for (int i = 0; i < 4; i++) MBARRIER_INIT(mb + i * 8, 1);
    }
    if (wid == 0) {
        TCGEN05_ALLOC(smem_to_u32(&s_tmemptr), 512);
        TCGEN05_RELINQ();
    }
    __syncthreads();
    uint32_t tbase = s_tmemptr;

    const size_t rowA0 = (size_t)blockIdx.y * 256;   // C row tile
    const size_t rowB0 = (size_t)blockIdx.x * 256;   // C col tile (= rows of Bt)

    // prefetch first STAGES chunks
    for (int c = 0; c < STAGES; c++) {
        load_tile(sb + c * STAGE_BYTES, sb + c * STAGE_BYTES + 32768,
                  A, Bt, rowA0, rowB0, c, tid);
        CP_COMMIT();
    }

    int ph0 = 0, ph1 = 0, ph2 = 0;
    for (int c = 0; c < CHUNKS; c++) {
        int s = c % STAGES;
        uint32_t stA = sb + s * STAGE_BYTES;
        uint32_t stB = stA + 32768;

        asm volatile("cp.async.wait_group %0;" :: "n"(STAGES - 1) : "memory");
        __syncthreads();

        if (wid == 0) {
            if (elect_one_pred()) {
                asm volatile("fence.proxy.async.shared::cta;" ::: "memory");
                uint64_t ad = MAKE_SMEM_DESC(stA);
                uint64_t bd = MAKE_SMEM_DESC(stB);
#pragma unroll
                for (int k = 0; k < 4; k++) {
                    bool acc = (c > 0) || (k > 0);
                    mma_f16_ss(tbase + 0,   ad + k * 2,        bd + k * 2, GEMM_IDESC, acc);
                    mma_f16_ss(tbase + 256, ad + 1024 + k * 2, bd + k * 2, GEMM_IDESC, acc);
                }
                TCGEN05_COMMIT(mb + s * 8);
            }
        }

        int nc = c + STAGES;
        if (nc < CHUNKS) {
            int ph = (s == 0) ? ph0 : (s == 1) ? ph1 : ph2;
            MBARRIER_WAIT_PARITY(mb + s * 8, ph);
            if (s == 0) ph0 ^= 1; else if (s == 1) ph1 ^= 1; else ph2 ^= 1;
            load_tile(stA, stB, A, Bt, rowA0, rowB0, nc, tid);
            CP_COMMIT();
        }
    }

    if (wid == 0 && elect_one_pred()) TCGEN05_COMMIT(mb + 24);
    MBARRIER_WAIT_PARITY(mb + 24, 0);
    TCGEN05_FENCE_AFTER();

    // epilogue: warps 0-3 -> rows 0..127 (TMEM cols 0..255),
    //           warps 4-7 -> rows 128..255 (TMEM cols 256..511)
    const int half = wid >> 2;
    const int sub  = wid & 3;
    size_t row = rowA0 + (size_t)half * 128 + sub * 32 + lid;
    float* crow = C + row * (size_t)NDIM + rowB0;
#pragma unroll 1
    for (int j = 0; j < 8; j++) {
        uint32_t r[32];
        TCGEN05_LD_32X32B_X32(r, tbase + half * 256 + j * 32);
        TCGEN05_WAIT_LD();
#pragma unroll
        for (int q = 0; q < 8; q++) {
            float4 v = make_float4(__uint_as_float(r[q * 4 + 0]), __uint_as_float(r[q * 4 + 1]),
                                   __uint_as_float(r[q * 4 + 2]), __uint_as_float(r[q * 4 + 3]));
            *reinterpret_cast<float4*>(crow + j * 32 + q * 4) = v;
        }
    }
    TCGEN05_FENCE_BEFORE();
    __syncthreads();
    if (wid == 0) TCGEN05_DEALLOC(tbase, 512);
#endif  // HAS_TCGEN05 (plain compute_103 pass compiles an empty stub; the
        // loader selects the sm_103a cubin on GB300)
}

// ---------------------------------------------------------------------------
// elementwise kernels
// ---------------------------------------------------------------------------
__global__ void build_S_kernel(const float* __restrict__ flat, float* __restrict__ S) {
    int idx = blockIdx.x * blockDim.x + threadIdx.x;
    int r = idx >> 11, c = idx & 2047;
    float v = 0.0f;
    if (r < c) {
        int off = r * (NDIM - 1) - (r * (r - 1)) / 2;
        v = flat[off + (c - r - 1)];
    } else if (r > c) {
        int off = c * (NDIM - 1) - (c * (c - 1)) / 2;
        v = -flat[off + (r - c - 1)];
    }
    S[idx] = v;
}

// C = beta*C + cI*I + cS*S + cS2*S2 + cS3*S3  (float4-vectorized)
__global__ void poly3_kernel(float* __restrict__ C, const float* __restrict__ S,
                             const float* __restrict__ S2, const float* __restrict__ S3,
                             float beta, float cI, float cS, float cS2, float cS3) {
    int idx = blockIdx.x * blockDim.x + threadIdx.x;   // over NN/4
    int flat = idx * 4;
    float4 s  = *(const float4*)(S  + flat);
    float4 s2 = *(const float4*)(S2 + flat);
    float4 s3 = *(const float4*)(S3 + flat);
    float4 c4 = make_float4(0.f, 0.f, 0.f, 0.f);
    if (beta != 0.0f) {
        float4 cc = *(const float4*)(C + flat);
        c4 = make_float4(beta * cc.x, beta * cc.y, beta * cc.z, beta * cc.w);
    }
    float o[4];
    o[0] = c4.x + cS * s.x + cS2 * s2.x + cS3 * s3.x;
    o[1] = c4.y + cS * s.y + cS2 * s2.y + cS3 * s3.y;
    o[2] = c4.z + cS * s.z + cS2 * s2.z + cS3 * s3.z;
    o[3] = c4.w + cS * s.w + cS2 * s2.w + cS3 * s3.w;
    int r = flat >> 11;
#pragma unroll
    for (int j = 0; j < 4; j++)
        if (r == ((flat + j) & 2047)) o[j] += cI;
    *(float4*)(C + flat) = make_float4(o[0], o[1], o[2], o[3]);
}

// split fp32 -> bf16 [hi | lo | hi], row-major, K=2048 -> 6144
__global__ void splitA_kernel(const float* __restrict__ in, __nv_bfloat16* __restrict__ out) {
    int idx = blockIdx.x * blockDim.x + threadIdx.x;
    int r = idx >> 11, c = idx & 2047;
    float x = in[idx];
    __nv_bfloat16 hi = __float2bfloat16_rn(x);
    __nv_bfloat16 lo = __float2bfloat16_rn(x - __bfloat162float(hi));
    size_t b = (size_t)r * K3;
    out[b + c] = hi;
    out[b + NDIM + c] = lo;
    out[b + 2 * NDIM + c] = hi;
}

// transpose + split fp32 B[K x N] -> bf16 Bt[N x 6144] = [hi | hi | lo]
__global__ void splitBt_kernel(const float* __restrict__ in, __nv_bfloat16* __restrict__ out) {
    __shared__ float t[32][33];
    int n0 = blockIdx.x * 32, k0 = blockIdx.y * 32;
    int tx = threadIdx.x, ty = threadIdx.y;
    t[ty][tx] = in[(size_t)(k0 + ty) * NDIM + n0 + tx];
    __syncthreads();
    float x = t[tx][ty];                    // = in[k0+tx][n0+ty]
    __nv_bfloat16 hi = __float2bfloat16_rn(x);
    __nv_bfloat16 lo = __float2bfloat16_rn(x - __bfloat162float(hi));
    size_t b = (size_t)(n0 + ty) * K3 + k0 + tx;
    out[b] = hi;
    out[b + NDIM] = hi;
    out[b + 2 * NDIM] = lo;
}

// ---------------------------------------------------------------------------
// launch: Paterson–Stockmeyer exp(S), all GEMMs on tcgen05 bf16-split
// ---------------------------------------------------------------------------
extern "C" void kernel_launch(void* const* d_in, const int* in_sizes, int n_in,
                              void* d_out, int out_size) {
    const float* X    = (const float*)d_in[0];
    const float* flat = (const float*)d_in[1];
    float*       Y    = (float*)d_out;

    float *S, *S2, *S3, *P, *R;
    __nv_bfloat16 *bufA, *SBt, *WBt, *XA;
    cudaGetSymbolAddress((void**)&S,  g_S);
    cudaGetSymbolAddress((void**)&S2, g_S2);
    cudaGetSymbolAddress((void**)&S3, g_S3);
    cudaGetSymbolAddress((void**)&P,  g_P);
    cudaGetSymbolAddress((void**)&R,  g_R);
    cudaGetSymbolAddress((void**)&bufA, g_bufA);
    cudaGetSymbolAddress((void**)&SBt,  g_SBt);
    cudaGetSymbolAddress((void**)&WBt,  g_WBt);
    cudaGetSymbolAddress((void**)&XA,   g_XA);

    cudaFuncSetAttribute(gemm_bf16_kernel, cudaFuncAttributeMaxDynamicSharedMemorySize, SMEM_DYN);

    const int NN = NDIM * NDIM;
    dim3 blk256(256);
    dim3 gT(64, 64), bT(32, 32);
    dim3 gNN(NDIM / 256, NDIM / 256);    // 8 x 8
    dim3 gY (NDIM / 256, BATCH / 256);   // 8 x 32

    // S from flat
    build_S_kernel<<<NN / 256, blk256>>>(flat, S);

    // S2 = S @ S
    splitA_kernel <<<NN / 256, blk256>>>(S, bufA);
    splitBt_kernel<<<gT, bT>>>(S, SBt);
    gemm_bf16_kernel<<<gNN, blk256, SMEM_DYN>>>(bufA, SBt, S2);

    // S3 = S2 @ S
    splitA_kernel<<<NN / 256, blk256>>>(S2, bufA);
    gemm_bf16_kernel<<<gNN, blk256, SMEM_DYN>>>(bufA, SBt, S3);

    // P = M2 = I/720 + S/5040 + S2/40320 + S3/362880
    poly3_kernel<<<NN / 1024, blk256>>>(P, S, S2, S3,
        0.0f, 1.0f / 720.0f, 1.0f / 5040.0f, 1.0f / 40320.0f, 1.0f / 362880.0f);

    // R = S3 @ M2 ; R += I/6 + S/24 + S2/120   -> M1
    splitA_kernel <<<NN / 256, blk256>>>(S3, bufA);
    splitBt_kernel<<<gT, bT>>>(P, WBt);
    gemm_bf16_kernel<<<gNN, blk256, SMEM_DYN>>>(bufA, WBt, R);
    poly3_kernel<<<NN / 1024, blk256>>>(R, S, S2, S3,
        1.0f, 1.0f / 6.0f, 1.0f / 24.0f, 1.0f / 120.0f, 0.0f);

    // P = S3 @ M1 ; P += I + S + S2/2          -> Q
    splitBt_kernel<<<gT, bT>>>(R, WBt);
    gemm_bf16_kernel<<<gNN, blk256, SMEM_DYN>>>(bufA, WBt, P);
    poly3_kernel<<<NN / 1024, blk256>>>(P, S, S2, S3,
        1.0f, 1.0f, 1.0f, 0.5f, 0.0f);

    // Y = X @ Q
    splitBt_kernel<<<gT, bT>>>(P, WBt);
    splitA_kernel<<<(BATCH * NDIM) / 256, blk256>>>(X, XA);
    gemm_bf16_kernel<<<gY, blk256, SMEM_DYN>>>(XA, WBt, Y);
}

// round 11
// speedup vs baseline: 6.5648x; 1.4579x over previous
#include <cuda_runtime.h>
#include <cuda_bf16.h>
#include <cstdint>

#define NDIM  2048
#define BATCH 8192
#define K3    (3 * NDIM)        // 6144 (split-K concatenation)
#define CHUNKS (K3 / 64)        // 96 K-chunks of 64 bf16
#define STAGES 3

#if defined(__CUDA_ARCH_FEAT_SM103_ALL) || defined(__CUDA_ARCH_FEAT_SM100_ALL)
#define HAS_TCGEN05 1
#else
#define HAS_TCGEN05 0
#endif

// ---------------- device scratch ----------------
__device__ float g_S [NDIM * NDIM];
__device__ float g_S2[NDIM * NDIM];
__device__ float g_S3[NDIM * NDIM];
__device__ float g_P [NDIM * NDIM];
__device__ float g_R [NDIM * NDIM];
__device__ __nv_bfloat16 g_bufA[NDIM  * K3];
__device__ __nv_bfloat16 g_SBt [NDIM  * K3];
__device__ __nv_bfloat16 g_WBt [NDIM  * K3];
__device__ __nv_bfloat16 g_XA  [BATCH * K3];

// ---------------- PTX helpers ----------------
__device__ __forceinline__ uint32_t smem_to_u32(const void* p) {
    uint32_t a;
    asm("{ .reg .u64 t; cvta.to.shared.u64 t, %1; cvt.u32.u64 %0, t; }"
        : "=r"(a) : "l"(p));
    return a;
}
#define SMEM_SWIZZLE_128B(o) ((o) ^ (((o) >> 3) & 0x70))

static constexpr uint64_t SMEM_DESC_BASE_SW128 =
    (uint64_t(2) << 61) | (uint64_t(1) << 46) | (uint64_t(64) << 32) | (uint64_t(1) << 16);
#define MAKE_SMEM_DESC(base) (SMEM_DESC_BASE_SW128 | ((uint64_t)((base) >> 4) & 0x3FFF))

#define MBARRIER_INIT(addr, cnt) \
    asm volatile("mbarrier.init.shared.b64 [%0], %1;" :: "r"((uint32_t)(addr)), "r"((uint32_t)(cnt)) : "memory")

#define MBARRIER_WAIT_PARITY(addr, par) do {                                   \
    uint32_t _m = (uint32_t)(addr); uint32_t _p = (uint32_t)(par); uint32_t _d;\
    asm volatile("{\n\t.reg .pred p;\n\t"                                       \
        "mbarrier.try_wait.parity.acquire.cta.shared::cta.b64 p, [%1], %2;\n\t" \
        "selp.b32 %0, 1, 0, p;\n\t}" : "=r"(_d) : "r"(_m), "r"(_p) : "memory"); \
    if (!_d) {                                                                  \
        asm volatile("{\n\t.reg .pred P1;\n\tWL_%=:\n\t"                        \
            "mbarrier.try_wait.parity.acquire.cta.shared::cta.b64 P1, [%0], %1, 0x989680;\n\t" \
            "@P1 bra.uni WD_%=;\n\tbra.uni WL_%=;\n\tWD_%=:\n\t}"               \
            :: "r"(_m), "r"(_p) : "memory");                                    \
    }                                                                           \
} while (0)

#define CP_ASYNC16(dst, src) \
    asm volatile("cp.async.cg.shared.global [%0], [%1], 16;" :: "r"(dst), "l"(src) : "memory")
#define CP_COMMIT() asm volatile("cp.async.commit_group;" ::: "memory")

#if HAS_TCGEN05
__device__ __forceinline__ uint32_t elect_one_pred() {
    uint32_t p;
    asm volatile("{\n\t.reg .pred p;\n\telect.sync _|p, 0xFFFFFFFF;\n\t"
                 "selp.b32 %0, 1, 0, p;\n\t}" : "=r"(p));
    return p;
}
#define TCGEN05_ALLOC(saddr, n) \
    asm volatile("tcgen05.alloc.cta_group::1.sync.aligned.shared::cta.b32 [%0], %1;" \
                 :: "r"((uint32_t)(saddr)), "r"((uint32_t)(n)) : "memory")
#define TCGEN05_DEALLOC(t, n) \
    asm volatile("tcgen05.dealloc.cta_group::1.sync.aligned.b32 %0, %1;" :: "r"(t), "r"((uint32_t)(n)))
#define TCGEN05_RELINQ() \
    asm volatile("tcgen05.relinquish_alloc_permit.cta_group::1.sync.aligned;")
#define TCGEN05_COMMIT(mb) \
    asm volatile("tcgen05.commit.cta_group::1.mbarrier::arrive::one.shared::cluster.b64 [%0];" \
                 :: "r"((uint32_t)(mb)) : "memory")
#define TCGEN05_FENCE_AFTER() asm volatile("tcgen05.fence::after_thread_sync;" ::: "memory")
#define TCGEN05_FENCE_BEFORE() asm volatile("tcgen05.fence::before_thread_sync;" ::: "memory")
#define TCGEN05_WAIT_LD() asm volatile("tcgen05.wait::ld.sync.aligned;" ::: "memory")

#define TCGEN05_LD_32X32B_X32(r, ta)                                            \
    asm volatile("tcgen05.ld.sync.aligned.32x32b.x32.b32 "                      \
        "{%0, %1, %2, %3, %4, %5, %6, %7, %8, %9, %10, %11, %12, %13, %14, %15,"\
        " %16, %17, %18, %19, %20, %21, %22, %23, %24, %25, %26, %27, %28, %29, %30, %31}, [%32];" \
        : "=r"((r)[0]),  "=r"((r)[1]),  "=r"((r)[2]),  "=r"((r)[3]),            \
          "=r"((r)[4]),  "=r"((r)[5]),  "=r"((r)[6]),  "=r"((r)[7]),            \
          "=r"((r)[8]),  "=r"((r)[9]),  "=r"((r)[10]), "=r"((r)[11]),           \
          "=r"((r)[12]), "=r"((r)[13]), "=r"((r)[14]), "=r"((r)[15]),           \
          "=r"((r)[16]), "=r"((r)[17]), "=r"((r)[18]), "=r"((r)[19]),           \
          "=r"((r)[20]), "=r"((r)[21]), "=r"((r)[22]), "=r"((r)[23]),           \
          "=r"((r)[24]), "=r"((r)[25]), "=r"((r)[26]), "=r"((r)[27]),           \
          "=r"((r)[28]), "=r"((r)[29]), "=r"((r)[30]), "=r"((r)[31])            \
        : "r"(ta))

// idesc: kind::f16, dtype F32, atype/btype BF16, N=256, M=128 (per dispatch)
static constexpr uint32_t GEMM_IDESC =
    (1u << 4) | (1u << 7) | (1u << 10) | ((256u / 8) << 17) | ((128u / 16) << 24);

__device__ __forceinline__ void mma_f16_ss(uint32_t d, uint64_t a, uint64_t b,
                                           uint32_t idesc, bool acc) {
    uint32_t en = acc ? 1u : 0u;
    asm volatile("{\n\t.reg .pred p;\n\tsetp.ne.u32 p, %5, 0;\n\t"
                 "tcgen05.mma.cta_group::1.kind::f16 [%0], %1, %2, %3, {%4, %4, %4, %4}, p;\n\t}"
                 :: "r"(d), "l"(a), "l"(b), "r"(idesc), "r"(0u), "r"(en) : "memory");
}
#endif  // HAS_TCGEN05

// ---------------------------------------------------------------------------
// bf16 split GEMM, templated on MT (number of 128-row M sub-tiles).
//   MT=1: 128x256 CTA tile (N^3 GEMMs, grid 8x16 = 128 CTAs)
//   MT=2: 256x256 CTA tile (Y GEMM, grid 8x32 = 256 CTAs)
// A  : [Mtot x 6144] row-major bf16 (hi | lo | hi)
// Bt : [2048 x 6144] row-major bf16 (hi | hi | lo)
// Pipeline: at iteration c issue MMAs for chunk c, then wait on chunk c-1's
// commit (issued last iteration — nearly complete) to release its stage and
// load chunk c+S-1 into it.  MMA execution overlaps wait+load (unlike the
// R10 version which waited on its OWN commit each chunk, draining the
// tensor pipe to idle every iteration).
// ---------------------------------------------------------------------------
template<int MT>
__device__ __forceinline__ void load_tile(uint32_t stA, uint32_t stB,
                                          const __nv_bfloat16* A, const __nv_bfloat16* Bt,
                                          size_t rowA0, size_t rowB0, int chunk, int tid) {
    const char* gA = (const char*)(A  + rowA0 * K3 + (size_t)chunk * 64);
    const char* gB = (const char*)(Bt + rowB0 * K3 + (size_t)chunk * 64);
#pragma unroll
    for (int i = 0; i < MT * 4; i++) {          // A: MT*128 rows x 8 x 16B
        int u = tid + i * 256;
        int row = u >> 3;
        int o16 = (u & 7) << 4;
        CP_ASYNC16(stA + SMEM_SWIZZLE_128B((uint32_t)(row * 128 + o16)),
                   gA + (size_t)row * (K3 * 2) + o16);
    }
#pragma unroll
    for (int i = 0; i < 8; i++) {               // B: 256 rows x 8 x 16B
        int u = tid + i * 256;
        int row = u >> 3;
        int o16 = (u & 7) << 4;
        CP_ASYNC16(stB + SMEM_SWIZZLE_128B((uint32_t)(row * 128 + o16)),
                   gB + (size_t)row * (K3 * 2) + o16);
    }
}

template<int MT>
__global__ __launch_bounds__(256, 1)
void gemm_bf16_kernel(const __nv_bfloat16* __restrict__ A,
                      const __nv_bfloat16* __restrict__ Bt,
                      float* __restrict__ C) {
#if HAS_TCGEN05
    constexpr int A_BYTES = MT * 16384;
    constexpr int STG_BYTES = A_BYTES + 32768;
    extern __shared__ char dyn[];
    __shared__ uint64_t s_mbar[4];
    __shared__ uint32_t s_tmemptr;

    const int tid = threadIdx.x;
    const int wid = tid >> 5;
    const int lid = tid & 31;
    uint32_t sb = (smem_to_u32(dyn) + 1023) & ~1023u;
    uint32_t mb = smem_to_u32(s_mbar);

    if (tid == 0) {
        for (int i = 0; i < 4; i++) MBARRIER_INIT(mb + i * 8, 1);
    }
    if (wid == 0) {
        TCGEN05_ALLOC(smem_to_u32(&s_tmemptr), 512);
        TCGEN05_RELINQ();
    }
    __syncthreads();
    uint32_t tbase = s_tmemptr;

    const size_t rowA0 = (size_t)blockIdx.y * (MT * 128);
    const size_t rowB0 = (size_t)blockIdx.x * 256;

    // prefetch chunks 0..STAGES-2 into stages 0..STAGES-2
    for (int c = 0; c < STAGES - 1; c++) {
        load_tile<MT>(sb + c * STG_BYTES, sb + c * STG_BYTES + A_BYTES,
                      A, Bt, rowA0, rowB0, c, tid);
        CP_COMMIT();
    }

    int ph0 = 0, ph1 = 0, ph2 = 0;
    for (int c = 0; c < CHUNKS; c++) {
        int sc = c % STAGES;
        uint32_t stA = sb + sc * STG_BYTES;
        uint32_t stB = stA + A_BYTES;

        asm volatile("cp.async.wait_group %0;" :: "n"(STAGES - 2) : "memory");
        __syncthreads();

        if (wid == 0) {
            if (elect_one_pred()) {
                asm volatile("fence.proxy.async.shared::cta;" ::: "memory");
                uint64_t ad = MAKE_SMEM_DESC(stA);
                uint64_t bd = MAKE_SMEM_DESC(stB);
#pragma unroll
                for (int k = 0; k < 4; k++) {
                    bool acc = (c > 0) || (k > 0);
                    mma_f16_ss(tbase, ad + k * 2, bd + k * 2, GEMM_IDESC, acc);
                    if (MT == 2)
                        mma_f16_ss(tbase + 256, ad + 1024 + k * 2, bd + k * 2, GEMM_IDESC, acc);
                }
                TCGEN05_COMMIT(mb + sc * 8);
            }
        }

        // release previous stage (chunk c-1's commit) and refill it
        int lc = c + STAGES - 1;
        if (lc < CHUNKS) {
            int sp = (c + STAGES - 1) % STAGES;   // == (c-1) mod STAGES
            if (c > 0) {
                int ph = (sp == 0) ? ph0 : (sp == 1) ? ph1 : ph2;
                MBARRIER_WAIT_PARITY(mb + sp * 8, ph);
                if (sp == 0) ph0 ^= 1; else if (sp == 1) ph1 ^= 1; else ph2 ^= 1;
            }
            load_tile<MT>(sb + sp * STG_BYTES, sb + sp * STG_BYTES + A_BYTES,
                          A, Bt, rowA0, rowB0, lc, tid);
            CP_COMMIT();
        }
    }

    if (wid == 0 && elect_one_pred()) TCGEN05_COMMIT(mb + 24);
    MBARRIER_WAIT_PARITY(mb + 24, 0);
    TCGEN05_FENCE_AFTER();

    if (MT == 2) {
        // warps 0-3: rows 0..127 (cols 0..255); warps 4-7: rows 128..255 (cols 256..511)
        const int half = wid >> 2;
        const int sub  = wid & 3;
        size_t row = rowA0 + (size_t)half * 128 + sub * 32 + lid;
        float* crow = C + row * (size_t)NDIM + rowB0;
#pragma unroll 1
        for (int j = 0; j < 8; j++) {
            uint32_t r[32];
            TCGEN05_LD_32X32B_X32(r, tbase + half * 256 + j * 32);
            TCGEN05_WAIT_LD();
#pragma unroll
            for (int q = 0; q < 8; q++)
                *reinterpret_cast<float4*>(crow + j * 32 + q * 4) =
                    make_float4(__uint_as_float(r[q*4+0]), __uint_as_float(r[q*4+1]),
                                __uint_as_float(r[q*4+2]), __uint_as_float(r[q*4+3]));
        }
    } else {
        // 128 rows x 256 cols: warp w -> rows (w&3)*32+lid, col half (w>>2)*128
        const int colh = wid >> 2;
        const int sub  = wid & 3;
        size_t row = rowA0 + sub * 32 + lid;
        float* crow = C + row * (size_t)NDIM + rowB0 + colh * 128;
#pragma unroll 1
        for (int j = 0; j < 4; j++) {
            uint32_t r[32];
            TCGEN05_LD_32X32B_X32(r, tbase + colh * 128 + j * 32);
            TCGEN05_WAIT_LD();
#pragma unroll
            for (int q = 0; q < 8; q++)
                *reinterpret_cast<float4*>(crow + j * 32 + q * 4) =
                    make_float4(__uint_as_float(r[q*4+0]), __uint_as_float(r[q*4+1]),
                                __uint_as_float(r[q*4+2]), __uint_as_float(r[q*4+3]));
        }
    }
    TCGEN05_FENCE_BEFORE();
    __syncthreads();
    if (wid == 0) TCGEN05_DEALLOC(tbase, 512);
#endif  // HAS_TCGEN05
}

// ---------------------------------------------------------------------------
// elementwise kernels (unchanged from R10 — measured negligible)
// ---------------------------------------------------------------------------
__global__ void build_S_kernel(const float* __restrict__ flat, float* __restrict__ S) {
    int idx = blockIdx.x * blockDim.x + threadIdx.x;
    int r = idx >> 11, c = idx & 2047;
    float v = 0.0f;
    if (r < c) {
        int off = r * (NDIM - 1) - (r * (r - 1)) / 2;
        v = flat[off + (c - r - 1)];
    } else if (r > c) {
        int off = c * (NDIM - 1) - (c * (c - 1)) / 2;
        v = -flat[off + (r - c - 1)];
    }
    S[idx] = v;
}

__global__ void poly3_kernel(float* __restrict__ C, const float* __restrict__ S,
                             const float* __restrict__ S2, const float* __restrict__ S3,
                             float beta, float cI, float cS, float cS2, float cS3) {
    int idx = blockIdx.x * blockDim.x + threadIdx.x;
    int flat = idx * 4;
    float4 s  = *(const float4*)(S  + flat);
    float4 s2 = *(const float4*)(S2 + flat);
    float4 s3 = *(const float4*)(S3 + flat);
    float4 c4 = make_float4(0.f, 0.f, 0.f, 0.f);
    if (beta != 0.0f) {
        float4 cc = *(const float4*)(C + flat);
        c4 = make_float4(beta * cc.x, beta * cc.y, beta * cc.z, beta * cc.w);
    }
    float o[4];
    o[0] = c4.x + cS * s.x + cS2 * s2.x + cS3 * s3.x;
    o[1] = c4.y + cS * s.y + cS2 * s2.y + cS3 * s3.y;
    o[2] = c4.z + cS * s.z + cS2 * s2.z + cS3 * s3.z;
    o[3] = c4.w + cS * s.w + cS2 * s2.w + cS3 * s3.w;
    int r = flat >> 11;
#pragma unroll
    for (int j = 0; j < 4; j++)
        if (r == ((flat + j) & 2047)) o[j] += cI;
    *(float4*)(C + flat) = make_float4(o[0], o[1], o[2], o[3]);
}

__global__ void splitA_kernel(const float* __restrict__ in, __nv_bfloat16* __restrict__ out) {
    int idx = blockIdx.x * blockDim.x + threadIdx.x;
    int r = idx >> 11, c = idx & 2047;
    float x = in[idx];
    __nv_bfloat16 hi = __float2bfloat16_rn(x);
    __nv_bfloat16 lo = __float2bfloat16_rn(x - __bfloat162float(hi));
    size_t b = (size_t)r * K3;
    out[b + c] = hi;
    out[b + NDIM + c] = lo;
    out[b + 2 * NDIM + c] = hi;
}

__global__ void splitBt_kernel(const float* __restrict__ in, __nv_bfloat16* __restrict__ out) {
    __shared__ float t[32][33];
    int n0 = blockIdx.x * 32, k0 = blockIdx.y * 32;
    int tx = threadIdx.x, ty = threadIdx.y;
    t[ty][tx] = in[(size_t)(k0 + ty) * NDIM + n0 + tx];
    __syncthreads();
    float x = t[tx][ty];
    __nv_bfloat16 hi = __float2bfloat16_rn(x);
    __nv_bfloat16 lo = __float2bfloat16_rn(x - __bfloat162float(hi));
    size_t b = (size_t)(n0 + ty) * K3 + k0 + tx;
    out[b] = hi;
    out[b + NDIM] = hi;
    out[b + 2 * NDIM] = lo;
}

// ---------------------------------------------------------------------------
extern "C" void kernel_launch(void* const* d_in, const int* in_sizes, int n_in,
                              void* d_out, int out_size) {
    const float* X    = (const float*)d_in[0];
    const float* flat = (const float*)d_in[1];
    float*       Y    = (float*)d_out;

    float *S, *S2, *S3, *P, *R;
    __nv_bfloat16 *bufA, *SBt, *WBt, *XA;
    cudaGetSymbolAddress((void**)&S,  g_S);
    cudaGetSymbolAddress((void**)&S2, g_S2);
    cudaGetSymbolAddress((void**)&S3, g_S3);
    cudaGetSymbolAddress((void**)&P,  g_P);
    cudaGetSymbolAddress((void**)&R,  g_R);
    cudaGetSymbolAddress((void**)&bufA, g_bufA);
    cudaGetSymbolAddress((void**)&SBt,  g_SBt);
    cudaGetSymbolAddress((void**)&WBt,  g_WBt);
    cudaGetSymbolAddress((void**)&XA,   g_XA);

    const int SMEM1 = STAGES * (16384 + 32768) + 1024;   // MT=1: 148480
    const int SMEM2 = STAGES * (32768 + 32768) + 1024;   // MT=2: 197632
    cudaFuncSetAttribute(gemm_bf16_kernel<1>, cudaFuncAttributeMaxDynamicSharedMemorySize, SMEM1);
    cudaFuncSetAttribute(gemm_bf16_kernel<2>, cudaFuncAttributeMaxDynamicSharedMemorySize, SMEM2);

    const int NN = NDIM * NDIM;
    dim3 blk256(256);
    dim3 gT(64, 64), bT(32, 32);
    dim3 gNN(NDIM / 256, NDIM / 128);    // MT=1: 8 x 16 = 128 CTAs
    dim3 gY (NDIM / 256, BATCH / 256);   // MT=2: 8 x 32 = 256 CTAs

    build_S_kernel<<<NN / 256, blk256>>>(flat, S);

    // S2 = S @ S
    splitA_kernel <<<NN / 256, blk256>>>(S, bufA);
    splitBt_kernel<<<gT, bT>>>(S, SBt);
    gemm_bf16_kernel<1><<<gNN, blk256, SMEM1>>>(bufA, SBt, S2);

    // S3 = S2 @ S
    splitA_kernel<<<NN / 256, blk256>>>(S2, bufA);
    gemm_bf16_kernel<1><<<gNN, blk256, SMEM1>>>(bufA, SBt, S3);

    // P = M2
    poly3_kernel<<<NN / 1024, blk256>>>(P, S, S2, S3,
        0.0f, 1.0f / 720.0f, 1.0f / 5040.0f, 1.0f / 40320.0f, 1.0f / 362880.0f);

    // R = S3 @ M2 + P1 -> M1
    splitA_kernel <<<NN / 256, blk256>>>(S3, bufA);
    splitBt_kernel<<<gT, bT>>>(P, WBt);
    gemm_bf16_kernel<1><<<gNN, blk256, SMEM1>>>(bufA, WBt, R);
    poly3_kernel<<<NN / 1024, blk256>>>(R, S, S2, S3,
        1.0f, 1.0f / 6.0f, 1.0f / 24.0f, 1.0f / 120.0f, 0.0f);

    // P = S3 @ M1 + P0 -> Q
    splitBt_kernel<<<gT, bT>>>(R, WBt);
    gemm_bf16_kernel<1><<<gNN, blk256, SMEM1>>>(bufA, WBt, P);
    poly3_kernel<<<NN / 1024, blk256>>>(P, S, S2, S3,
        1.0f, 1.0f, 1.0f, 0.5f, 0.0f);

    // Y = X @ Q
    splitBt_kernel<<<gT, bT>>>(P, WBt);
    splitA_kernel<<<(BATCH * NDIM) / 256, blk256>>>(X, XA);
    gemm_bf16_kernel<2><<<gY, blk256, SMEM2>>>(XA, WBt, Y);
}

// round 15
// speedup vs baseline: 7.0390x; 1.0722x over previous
#include <cuda_runtime.h>
#include <cuda_bf16.h>
#include <cstdint>

#define NDIM  2048
#define BATCH 8192
#define K3    (3 * NDIM)        // 6144 (split-K concatenation)
#define CHUNKS (K3 / 64)        // 96 K-chunks of 64 bf16

#if defined(__CUDA_ARCH_FEAT_SM103_ALL) || defined(__CUDA_ARCH_FEAT_SM100_ALL)
#define HAS_TCGEN05 1
#else
#define HAS_TCGEN05 0
#endif

// ---------------- device scratch ----------------
__device__ float g_S [NDIM * NDIM];
__device__ float g_S2[NDIM * NDIM];
__device__ float g_U [NDIM * NDIM];           // S^3
__device__ __nv_bfloat16 g_A1  [NDIM  * K3];  // A-split buffer 1 (S, then B2)
__device__ __nv_bfloat16 g_A2  [NDIM  * K3];  // A-split buffer 2 (S2, then M1)
__device__ __nv_bfloat16 g_SBtN[NDIM  * K3];  // Bt-split of -S  (hi|hi|lo)
__device__ __nv_bfloat16 g_UBtN[NDIM  * K3];  // Bt-split of -U  (hi|hi|lo)
__device__ __nv_bfloat16 g_WBt [NDIM  * K3];  // Bt-split of W=exp(-S) (hi|hi|lo)
__device__ __nv_bfloat16 g_XA  [BATCH * K3];  // A-split of X

// ---------------- PTX helpers ----------------
__device__ __forceinline__ uint32_t smem_to_u32(const void* p) {
    uint32_t a;
    asm("{ .reg .u64 t; cvta.to.shared.u64 t, %1; cvt.u32.u64 %0, t; }"
        : "=r"(a) : "l"(p));
    return a;
}
#define SMEM_SWIZZLE_128B(o) ((o) ^ (((o) >> 3) & 0x70))

static constexpr uint64_t SMEM_DESC_BASE_SW128 =
    (uint64_t(2) << 61) | (uint64_t(1) << 46) | (uint64_t(64) << 32) | (uint64_t(1) << 16);
#define MAKE_SMEM_DESC(base) (SMEM_DESC_BASE_SW128 | ((uint64_t)((base) >> 4) & 0x3FFF))

#define MBARRIER_INIT(addr, cnt) \
    asm volatile("mbarrier.init.shared.b64 [%0], %1;" :: "r"((uint32_t)(addr)), "r"((uint32_t)(cnt)) : "memory")

#define MBARRIER_WAIT_PARITY(addr, par) do {                                   \
    uint32_t _m = (uint32_t)(addr); uint32_t _p = (uint32_t)(par); uint32_t _d;\
    asm volatile("{\n\t.reg .pred p;\n\t"                                       \
        "mbarrier.try_wait.parity.acquire.cta.shared::cta.b64 p, [%1], %2;\n\t" \
        "selp.b32 %0, 1, 0, p;\n\t}" : "=r"(_d) : "r"(_m), "r"(_p) : "memory"); \
    if (!_d) {                                                                  \
        asm volatile("{\n\t.reg .pred P1;\n\tWL_%=:\n\t"                        \
            "mbarrier.try_wait.parity.acquire.cta.shared::cta.b64 P1, [%0], %1, 0x989680;\n\t" \
            "@P1 bra.uni WD_%=;\n\tbra.uni WL_%=;\n\tWD_%=:\n\t}"               \
            :: "r"(_m), "r"(_p) : "memory");                                    \
    }                                                                           \
} while (0)

#define CP_ASYNC16(dst, src) \
    asm volatile("cp.async.cg.shared.global [%0], [%1], 16;" :: "r"(dst), "l"(src) : "memory")
#define CP_COMMIT() asm volatile("cp.async.commit_group;" ::: "memory")

#if HAS_TCGEN05
__device__ __forceinline__ uint32_t elect_one_pred() {
    uint32_t p;
    asm volatile("{\n\t.reg .pred p;\n\telect.sync _|p, 0xFFFFFFFF;\n\t"
                 "selp.b32 %0, 1, 0, p;\n\t}" : "=r"(p));
    return p;
}
#define TCGEN05_ALLOC(saddr, n) \
    asm volatile("tcgen05.alloc.cta_group::1.sync.aligned.shared::cta.b32 [%0], %1;" \
                 :: "r"((uint32_t)(saddr)), "r"((uint32_t)(n)) : "memory")
#define TCGEN05_DEALLOC(t, n) \
    asm volatile("tcgen05.dealloc.cta_group::1.sync.aligned.b32 %0, %1;" :: "r"(t), "r"((uint32_t)(n)))
#define TCGEN05_RELINQ() \
    asm volatile("tcgen05.relinquish_alloc_permit.cta_group::1.sync.aligned;")
#define TCGEN05_COMMIT(mb) \
    asm volatile("tcgen05.commit.cta_group::1.mbarrier::arrive::one.shared::cluster.b64 [%0];" \
                 :: "r"((uint32_t)(mb)) : "memory")
#define TCGEN05_FENCE_AFTER() asm volatile("tcgen05.fence::after_thread_sync;" ::: "memory")
#define TCGEN05_FENCE_BEFORE() asm volatile("tcgen05.fence::before_thread_sync;" ::: "memory")
#define TCGEN05_WAIT_LD() asm volatile("tcgen05.wait::ld.sync.aligned;" ::: "memory")

#define TCGEN05_LD_32X32B_X32(r, ta)                                            \
    asm volatile("tcgen05.ld.sync.aligned.32x32b.x32.b32 "                      \
        "{%0, %1, %2, %3, %4, %5, %6, %7, %8, %9, %10, %11, %12, %13, %14, %15,"\
        " %16, %17, %18, %19, %20, %21, %22, %23, %24, %25, %26, %27, %28, %29, %30, %31}, [%32];" \
        : "=r"((r)[0]),  "=r"((r)[1]),  "=r"((r)[2]),  "=r"((r)[3]),            \
          "=r"((r)[4]),  "=r"((r)[5]),  "=r"((r)[6]),  "=r"((r)[7]),            \
          "=r"((r)[8]),  "=r"((r)[9]),  "=r"((r)[10]), "=r"((r)[11]),           \
          "=r"((r)[12]), "=r"((r)[13]), "=r"((r)[14]), "=r"((r)[15]),           \
          "=r"((r)[16]), "=r"((r)[17]), "=r"((r)[18]), "=r"((r)[19]),           \
          "=r"((r)[20]), "=r"((r)[21]), "=r"((r)[22]), "=r"((r)[23]),           \
          "=r"((r)[24]), "=r"((r)[25]), "=r"((r)[26]), "=r"((r)[27]),           \
          "=r"((r)[28]), "=r"((r)[29]), "=r"((r)[30]), "=r"((r)[31])            \
        : "r"(ta))

// idesc: kind::f16, dtype F32, atype/btype BF16, N=256, M=128 (per dispatch)
static constexpr uint32_t GEMM_IDESC =
    (1u << 4) | (1u << 7) | (1u << 10) | ((256u / 8) << 17) | ((128u / 16) << 24);

__device__ __forceinline__ void mma_f16_ss(uint32_t d, uint64_t a, uint64_t b,
                                           uint32_t idesc, bool acc) {
    uint32_t en = acc ? 1u : 0u;
    asm volatile("{\n\t.reg .pred p;\n\tsetp.ne.u32 p, %5, 0;\n\t"
                 "tcgen05.mma.cta_group::1.kind::f16 [%0], %1, %2, %3, {%4, %4, %4, %4}, p;\n\t}"
                 :: "r"(d), "l"(a), "l"(b), "r"(idesc), "r"(0u), "r"(en) : "memory");
}
#endif  // HAS_TCGEN05

// split helpers: v -> (hi, lo) bf16 pair
__device__ __forceinline__ void split_bf(float v, unsigned short& h, unsigned short& l) {
    __nv_bfloat16 bh = __float2bfloat16_rn(v);
    __nv_bfloat16 bl = __float2bfloat16_rn(v - __bfloat162float(bh));
    h = __bfloat16_as_ushort(bh);
    l = __bfloat16_as_ushort(bl);
}
__device__ __forceinline__ uint2 pack4(unsigned short a, unsigned short b,
                                       unsigned short c, unsigned short d) {
    return make_uint2((uint32_t)a | ((uint32_t)b << 16),
                      (uint32_t)c | ((uint32_t)d << 16));
}

// ---------------------------------------------------------------------------
// GEMM template. MT: 1 -> 128x256 tile, 2 -> 256x256. EPI epilogue mode:
//  0: plain fp32 C
//  1: fp32 C + A-split(t)      -> aux (hi|lo|hi)
//  2: fp32 C + Bt-split(-t)    -> aux (hi|hi|lo)      [for antisymmetric U]
//  3: t += B1 poly (-I/6 + S/24 - S2/120); A-split only -> aux
//  4: t += A0 poly ( I   - S   + S2/2  ); Bt-split only -> aux  [W = exp(-S)]
// ---------------------------------------------------------------------------
template<int MT>
__device__ __forceinline__ void load_tile(uint32_t stA, uint32_t stB,
                                          const __nv_bfloat16* A, const __nv_bfloat16* Bt,
                                          size_t rowA0, size_t rowB0, int chunk, int tid) {
    const char* gA = (const char*)(A  + rowA0 * K3 + (size_t)chunk * 64);
    const char* gB = (const char*)(Bt + rowB0 * K3 + (size_t)chunk * 64);
#pragma unroll
    for (int i = 0; i < MT * 4; i++) {
        int u = tid + i * 256;
        int row = u >> 3;
        int o16 = (u & 7) << 4;
        CP_ASYNC16(stA + SMEM_SWIZZLE_128B((uint32_t)(row * 128 + o16)),
                   gA + (size_t)row * (K3 * 2) + o16);
    }
#pragma unroll
    for (int i = 0; i < 8; i++) {
        int u = tid + i * 256;
        int row = u >> 3;
        int o16 = (u & 7) << 4;
        CP_ASYNC16(stB + SMEM_SWIZZLE_128B((uint32_t)(row * 128 + o16)),
                   gB + (size_t)row * (K3 * 2) + o16);
    }
}

template<int MT, int EPI>
__global__ __launch_bounds__(256, 1)
void gemm_bf16_kernel(const __nv_bfloat16* __restrict__ A,
                      const __nv_bfloat16* __restrict__ Bt,
                      float* __restrict__ C,
                      __nv_bfloat16* __restrict__ aux,
                      const float* __restrict__ PS,
                      const float* __restrict__ PS2) {
#if HAS_TCGEN05
    constexpr int NST = (MT == 1) ? 4 : 3;
    constexpr int A_BYTES = MT * 16384;
    constexpr int STG_BYTES = A_BYTES + 32768;
    extern __shared__ char dyn[];
    __shared__ uint64_t s_mbar[5];
    __shared__ uint32_t s_tmemptr;

    const int tid = threadIdx.x;
    const int wid = tid >> 5;
    const int lid = tid & 31;
    uint32_t sb = (smem_to_u32(dyn) + 1023) & ~1023u;
    uint32_t mb = smem_to_u32(s_mbar);

    if (tid == 0) {
        for (int i = 0; i < 5; i++) MBARRIER_INIT(mb + i * 8, 1);
    }
    if (wid == 0) {
        TCGEN05_ALLOC(smem_to_u32(&s_tmemptr), 512);
        TCGEN05_RELINQ();
    }
    __syncthreads();
    uint32_t tbase = s_tmemptr;

    const size_t rowA0 = (size_t)blockIdx.y * (MT * 128);
    const size_t rowB0 = (size_t)blockIdx.x * 256;

    for (int c = 0; c < NST - 1; c++) {
        load_tile<MT>(sb + c * STG_BYTES, sb + c * STG_BYTES + A_BYTES,
                      A, Bt, rowA0, rowB0, c, tid);
        CP_COMMIT();
    }

    int ph0 = 0, ph1 = 0, ph2 = 0, ph3 = 0;
    for (int c = 0; c < CHUNKS; c++) {
        int sc = c % NST;
        uint32_t stA = sb + sc * STG_BYTES;
        uint32_t stB = stA + A_BYTES;

        asm volatile("cp.async.wait_group %0;" :: "n"(NST - 2) : "memory");
        __syncthreads();

        if (wid == 0) {
            if (elect_one_pred()) {
                asm volatile("fence.proxy.async.shared::cta;" ::: "memory");
                uint64_t ad = MAKE_SMEM_DESC(stA);
                uint64_t bd = MAKE_SMEM_DESC(stB);
#pragma unroll
                for (int k = 0; k < 4; k++) {
                    bool acc = (c > 0) || (k > 0);
                    mma_f16_ss(tbase, ad + k * 2, bd + k * 2, GEMM_IDESC, acc);
                    if (MT == 2)
                        mma_f16_ss(tbase + 256, ad + 1024 + k * 2, bd + k * 2, GEMM_IDESC, acc);
                }
                TCGEN05_COMMIT(mb + sc * 8);
            }
        }

        int lc = c + NST - 1;
        if (lc < CHUNKS) {
            int sp = (c + NST - 1) % NST;   // == (c-1) mod NST
            if (c > 0) {
                int ph = (sp == 0) ? ph0 : (sp == 1) ? ph1 : (sp == 2) ? ph2 : ph3;
                MBARRIER_WAIT_PARITY(mb + sp * 8, ph);
                if (sp == 0) ph0 ^= 1; else if (sp == 1) ph1 ^= 1;
                else if (sp == 2) ph2 ^= 1; else ph3 ^= 1;
            }
            load_tile<MT>(sb + sp * STG_BYTES, sb + sp * STG_BYTES + A_BYTES,
                          A, Bt, rowA0, rowB0, lc, tid);
            CP_COMMIT();
        }
    }

    if (wid == 0 && elect_one_pred()) TCGEN05_COMMIT(mb + 32);
    MBARRIER_WAIT_PARITY(mb + 32, 0);
    TCGEN05_FENCE_AFTER();

    if (MT == 2) {
        const int half = wid >> 2;
        const int sub  = wid & 3;
        size_t row = rowA0 + (size_t)half * 128 + sub * 32 + lid;
        float* crow = C + row * (size_t)NDIM + rowB0;
#pragma unroll 1
        for (int j = 0; j < 8; j++) {
            uint32_t r[32];
            TCGEN05_LD_32X32B_X32(r, tbase + half * 256 + j * 32);
            TCGEN05_WAIT_LD();
#pragma unroll
            for (int q = 0; q < 8; q++)
                *reinterpret_cast<float4*>(crow + j * 32 + q * 4) =
                    make_float4(__uint_as_float(r[q*4+0]), __uint_as_float(r[q*4+1]),
                                __uint_as_float(r[q*4+2]), __uint_as_float(r[q*4+3]));
        }
    } else {
        const int colh = wid >> 2;
        const int sub  = wid & 3;
        size_t row = rowA0 + sub * 32 + lid;
        int colbase = (int)rowB0 + colh * 128;
#pragma unroll 1
        for (int j = 0; j < 4; j++) {
            uint32_t r[32];
            TCGEN05_LD_32X32B_X32(r, tbase + colh * 128 + j * 32);
            TCGEN05_WAIT_LD();
#pragma unroll
            for (int q = 0; q < 8; q++) {
                int col = colbase + j * 32 + q * 4;
                float v[4];
#pragma unroll
                for (int i = 0; i < 4; i++) v[i] = __uint_as_float(r[q * 4 + i]);
                if (EPI == 3 || EPI == 4) {
                    float4 s4  = *reinterpret_cast<const float4*>(PS  + row * NDIM + col);
                    float4 s24 = *reinterpret_cast<const float4*>(PS2 + row * NDIM + col);
                    const float* sp  = &s4.x;
                    const float* sp2 = &s24.x;
#pragma unroll
                    for (int i = 0; i < 4; i++) {
                        if (EPI == 3)
                            v[i] += sp[i] * (1.0f/24.0f) - sp2[i] * (1.0f/120.0f)
                                    - ((row == (size_t)(col + i)) ? (1.0f/6.0f) : 0.0f);
                        else
                            v[i] += -sp[i] + sp2[i] * 0.5f
                                    + ((row == (size_t)(col + i)) ? 1.0f : 0.0f);
                    }
                }
                if (EPI == 1 || EPI == 2)
                    *reinterpret_cast<float4*>(C + row * NDIM + col) =
                        make_float4(v[0], v[1], v[2], v[3]);
                // split
                unsigned short h[4], l[4];
#pragma unroll
                for (int i = 0; i < 4; i++) {
                    float sv = (EPI == 2) ? -v[i] : v[i];
                    split_bf(sv, h[i], l[i]);
                }
                uint2 hp = pack4(h[0], h[1], h[2], h[3]);
                uint2 lp = pack4(l[0], l[1], l[2], l[3]);
                __nv_bfloat16* base = aux + row * K3 + col;
                if (EPI == 1 || EPI == 3) {          // A-split: hi | lo | hi
                    *reinterpret_cast<uint2*>(base) = hp;
                    *reinterpret_cast<uint2*>(base + NDIM) = lp;
                    *reinterpret_cast<uint2*>(base + 2 * NDIM) = hp;
                } else {                              // Bt-split: hi | hi | lo
                    *reinterpret_cast<uint2*>(base) = hp;
                    *reinterpret_cast<uint2*>(base + NDIM) = hp;
                    *reinterpret_cast<uint2*>(base + 2 * NDIM) = lp;
                }
            }
        }
    }
    TCGEN05_FENCE_BEFORE();
    __syncthreads();
    if (wid == 0) TCGEN05_DEALLOC(tbase, 512);
#endif  // HAS_TCGEN05
}

// ---------------------------------------------------------------------------
// elementwise kernels (3 total)
// ---------------------------------------------------------------------------
// build S; write fp32 S, A-split(S) and Bt-split(-S)
__global__ void build_S_fused(const float* __restrict__ flat, float* __restrict__ S,
                              __nv_bfloat16* __restrict__ ASp, __nv_bfloat16* __restrict__ BtN) {
    int idx = blockIdx.x * blockDim.x + threadIdx.x;
    int r = idx >> 11, c = idx & 2047;
    float v = 0.0f;
    if (r < c) {
        int off = r * (NDIM - 1) - (r * (r - 1)) / 2;
        v = flat[off + (c - r - 1)];
    } else if (r > c) {
        int off = c * (NDIM - 1) - (c * (c - 1)) / 2;
        v = -flat[off + (r - c - 1)];
    }
    S[idx] = v;
    unsigned short h, l, nh, nl;
    split_bf(v, h, l);
    split_bf(-v, nh, nl);
    size_t b = (size_t)r * K3 + c;
    ASp[b] = __ushort_as_bfloat16(h);
    ASp[b + NDIM] = __ushort_as_bfloat16(l);
    ASp[b + 2 * NDIM] = __ushort_as_bfloat16(h);
    BtN[b] = __ushort_as_bfloat16(nh);
    BtN[b + NDIM] = __ushort_as_bfloat16(nh);
    BtN[b + 2 * NDIM] = __ushort_as_bfloat16(nl);
}

// B2 = I/720 - S/5040 + S2/40320 - U/362880 ; write A-split(B2)
__global__ void b2split_kernel(const float* __restrict__ S, const float* __restrict__ S2,
                               const float* __restrict__ U, __nv_bfloat16* __restrict__ ASp) {
    int idx = blockIdx.x * blockDim.x + threadIdx.x;   // over NN/4
    int flat = idx * 4;
    int r = flat >> 11;
    float4 s  = *(const float4*)(S  + flat);
    float4 s2 = *(const float4*)(S2 + flat);
    float4 u  = *(const float4*)(U  + flat);
    const float* sp  = &s.x;
    const float* sp2 = &s2.x;
    const float* up  = &u.x;
    unsigned short h[4], l[4];
#pragma unroll
    for (int i = 0; i < 4; i++) {
        float v = -sp[i] * (1.0f/5040.0f) + sp2[i] * (1.0f/40320.0f) - up[i] * (1.0f/362880.0f);
        if (r == ((flat + i) & 2047)) v += 1.0f/720.0f;
        split_bf(v, h[i], l[i]);
    }
    uint2 hp = pack4(h[0], h[1], h[2], h[3]);
    uint2 lp = pack4(l[0], l[1], l[2], l[3]);
    __nv_bfloat16* base = ASp + (size_t)r * K3 + (flat & 2047);
    *reinterpret_cast<uint2*>(base) = hp;
    *reinterpret_cast<uint2*>(base + NDIM) = lp;
    *reinterpret_cast<uint2*>(base + 2 * NDIM) = hp;
}

// X -> A-split(X), vectorized
__global__ void splitAX_kernel(const float* __restrict__ in, __nv_bfloat16* __restrict__ out) {
    int idx = blockIdx.x * blockDim.x + threadIdx.x;   // over BATCH*NDIM/4
    int flat4 = idx * 4;
    int r = flat4 >> 11;
    int c = flat4 & 2047;
    float4 x = *(const float4*)(in + (size_t)flat4);
    const float* xp = &x.x;
    unsigned short h[4], l[4];
#pragma unroll
    for (int i = 0; i < 4; i++) split_bf(xp[i], h[i], l[i]);
    uint2 hp = pack4(h[0], h[1], h[2], h[3]);
    uint2 lp = pack4(l[0], l[1], l[2], l[3]);
    __nv_bfloat16* base = out + (size_t)r * K3 + c;
    *reinterpret_cast<uint2*>(base) = hp;
    *reinterpret_cast<uint2*>(base + NDIM) = lp;
    *reinterpret_cast<uint2*>(base + 2 * NDIM) = hp;
}

// ---------------------------------------------------------------------------
// W = exp(-S) = A0 + (B1 + B2*U)*U   (U = S^3; all factors commute)
// A0 = I - S + S2/2 ; B1 = -I/6 + S/24 - S2/120
// B2 = I/720 - S/5040 + S2/40320 - U/362880
// Y = X @ exp(S); Bt(exp(S)) = exp(S)^T row-major = W row-major.
// ---------------------------------------------------------------------------
extern "C" void kernel_launch(void* const* d_in, const int* in_sizes, int n_in,
                              void* d_out, int out_size) {
    const float* X    = (const float*)d_in[0];
    const float* flat = (const float*)d_in[1];
    float*       Y    = (float*)d_out;

    float *S, *S2, *U;
    __nv_bfloat16 *A1, *A2, *SBtN, *UBtN, *WBt, *XA;
    cudaGetSymbolAddress((void**)&S,  g_S);
    cudaGetSymbolAddress((void**)&S2, g_S2);
    cudaGetSymbolAddress((void**)&U,  g_U);
    cudaGetSymbolAddress((void**)&A1, g_A1);
    cudaGetSymbolAddress((void**)&A2, g_A2);
    cudaGetSymbolAddress((void**)&SBtN, g_SBtN);
    cudaGetSymbolAddress((void**)&UBtN, g_UBtN);
    cudaGetSymbolAddress((void**)&WBt,  g_WBt);
    cudaGetSymbolAddress((void**)&XA,   g_XA);

    const int SMEM1 = 4 * (16384 + 32768) + 1024;   // MT=1, 4 stages: 197632
    const int SMEM2 = 3 * (32768 + 32768) + 1024;   // MT=2, 3 stages: 197632
    cudaFuncSetAttribute(gemm_bf16_kernel<1,1>, cudaFuncAttributeMaxDynamicSharedMemorySize, SMEM1);
    cudaFuncSetAttribute(gemm_bf16_kernel<1,2>, cudaFuncAttributeMaxDynamicSharedMemorySize, SMEM1);
    cudaFuncSetAttribute(gemm_bf16_kernel<1,3>, cudaFuncAttributeMaxDynamicSharedMemorySize, SMEM1);
    cudaFuncSetAttribute(gemm_bf16_kernel<1,4>, cudaFuncAttributeMaxDynamicSharedMemorySize, SMEM1);
    cudaFuncSetAttribute(gemm_bf16_kernel<2,0>, cudaFuncAttributeMaxDynamicSharedMemorySize, SMEM2);

    const int NN = NDIM * NDIM;
    dim3 blk256(256);
    dim3 gNN(NDIM / 256, NDIM / 128);    // MT=1: 8 x 16 = 128 CTAs
    dim3 gY (NDIM / 256, BATCH / 256);   // MT=2: 8 x 32 = 256 CTAs

    // 1. S, A-split(S) -> A1, Bt-split(-S) -> SBtN
    build_S_fused<<<NN / 256, blk256>>>(flat, S, A1, SBtN);

    // X -> XA (independent; schedule early)
    splitAX_kernel<<<(BATCH * NDIM) / 1024, blk256>>>(X, XA);

    // 2. S2 = S@S ; epi: fp32 S2 + A-split(S2) -> A2
    gemm_bf16_kernel<1,1><<<gNN, blk256, SMEM1>>>(A1, SBtN, S2, A2, nullptr, nullptr);

    // 3. U = S2@S ; epi: fp32 U + Bt-split(-U) -> UBtN
    gemm_bf16_kernel<1,2><<<gNN, blk256, SMEM1>>>(A2, SBtN, U, UBtN, nullptr, nullptr);

    // 4. A-split(B2) -> A1
    b2split_kernel<<<NN / 1024, blk256>>>(S, S2, U, A1);

    // 5. T1 = B2@U ; epi: M1 = B1 + T1, A-split(M1) -> A2
    gemm_bf16_kernel<1,3><<<gNN, blk256, SMEM1>>>(A1, UBtN, nullptr, A2, S, S2);

    // 6. T0 = M1@U ; epi: W = A0 + T0, Bt-split(W) -> WBt
    gemm_bf16_kernel<1,4><<<gNN, blk256, SMEM1>>>(A2, UBtN, nullptr, WBt, S, S2);

    // 7. Y = XA @ WBt
    gemm_bf16_kernel<2,0><<<gY, blk256, SMEM2>>>(XA, WBt, Y, nullptr, nullptr, nullptr);
}

// round 17
// speedup vs baseline: 8.7844x; 1.2480x over previous
#include <cuda_runtime.h>
#include <cuda_bf16.h>
#include <cstdint>

#define NDIM  2048
#define BATCH 8192
#define K3    (3 * NDIM)        // 6144 (split-K concatenation)
#define CHUNKS (K3 / 64)        // 96 K-chunks of 64 bf16

#if defined(__CUDA_ARCH_FEAT_SM103_ALL) || defined(__CUDA_ARCH_FEAT_SM100_ALL)
#define HAS_TCGEN05 1
#else
#define HAS_TCGEN05 0
#endif

// ---------------- device scratch ----------------
__device__ float g_S [NDIM * NDIM];
__device__ float g_S2[NDIM * NDIM];
__device__ float g_U [NDIM * NDIM];           // S^3
__device__ __nv_bfloat16 g_A1  [NDIM  * K3];  // A-split buffer 1 (S, then B2)
__device__ __nv_bfloat16 g_A2  [NDIM  * K3];  // A-split buffer 2 (S2, then M1)
__device__ __nv_bfloat16 g_SBtN[NDIM  * K3];  // Bt-split of -S  (hi|hi|lo)
__device__ __nv_bfloat16 g_UBtN[NDIM  * K3];  // Bt-split of -U  (hi|hi|lo)
__device__ __nv_bfloat16 g_WBt [NDIM  * K3];  // Bt-split of W=exp(-S) (hi|hi|lo)
__device__ __nv_bfloat16 g_XA  [BATCH * K3];  // A-split of X

// ---------------- PTX helpers ----------------
__device__ __forceinline__ uint32_t smem_to_u32(const void* p) {
    uint32_t a;
    asm("{ .reg .u64 t; cvta.to.shared.u64 t, %1; cvt.u32.u64 %0, t; }"
        : "=r"(a) : "l"(p));
    return a;
}
#define SMEM_SWIZZLE_128B(o) ((o) ^ (((o) >> 3) & 0x70))

static constexpr uint64_t SMEM_DESC_BASE_SW128 =
    (uint64_t(2) << 61) | (uint64_t(1) << 46) | (uint64_t(64) << 32) | (uint64_t(1) << 16);
#define MAKE_SMEM_DESC(base) (SMEM_DESC_BASE_SW128 | ((uint64_t)((base) >> 4) & 0x3FFF))

#define MBARRIER_INIT(addr, cnt) \
    asm volatile("mbarrier.init.shared.b64 [%0], %1;" :: "r"((uint32_t)(addr)), "r"((uint32_t)(cnt)) : "memory")

#define MBARRIER_WAIT_PARITY(addr, par) do {                                   \
    uint32_t _m = (uint32_t)(addr); uint32_t _p = (uint32_t)(par); uint32_t _d;\
    asm volatile("{\n\t.reg .pred p;\n\t"                                       \
        "mbarrier.try_wait.parity.acquire.cta.shared::cta.b64 p, [%1], %2;\n\t" \
        "selp.b32 %0, 1, 0, p;\n\t}" : "=r"(_d) : "r"(_m), "r"(_p) : "memory"); \
    if (!_d) {                                                                  \
        asm volatile("{\n\t.reg .pred P1;\n\tWL_%=:\n\t"                        \
            "mbarrier.try_wait.parity.acquire.cta.shared::cta.b64 P1, [%0], %1, 0x989680;\n\t" \
            "@P1 bra.uni WD_%=;\n\tbra.uni WL_%=;\n\tWD_%=:\n\t}"               \
            :: "r"(_m), "r"(_p) : "memory");                                    \
    }                                                                           \
} while (0)

#define CP_ASYNC16(dst, src) \
    asm volatile("cp.async.cg.shared.global [%0], [%1], 16;" :: "r"(dst), "l"(src) : "memory")
#define CP_COMMIT() asm volatile("cp.async.commit_group;" ::: "memory")

#if HAS_TCGEN05
__device__ __forceinline__ uint32_t elect_one_pred() {
    uint32_t p;
    asm volatile("{\n\t.reg .pred p;\n\telect.sync _|p, 0xFFFFFFFF;\n\t"
                 "selp.b32 %0, 1, 0, p;\n\t}" : "=r"(p));
    return p;
}
#define TCGEN05_ALLOC(saddr, n) \
    asm volatile("tcgen05.alloc.cta_group::1.sync.aligned.shared::cta.b32 [%0], %1;" \
                 :: "r"((uint32_t)(saddr)), "r"((uint32_t)(n)) : "memory")
#define TCGEN05_DEALLOC(t, n) \
    asm volatile("tcgen05.dealloc.cta_group::1.sync.aligned.b32 %0, %1;" :: "r"(t), "r"((uint32_t)(n)))
#define TCGEN05_RELINQ() \
    asm volatile("tcgen05.relinquish_alloc_permit.cta_group::1.sync.aligned;")
#define TCGEN05_COMMIT(mb) \
    asm volatile("tcgen05.commit.cta_group::1.mbarrier::arrive::one.shared::cluster.b64 [%0];" \
                 :: "r"((uint32_t)(mb)) : "memory")
#define TCGEN05_FENCE_AFTER() asm volatile("tcgen05.fence::after_thread_sync;" ::: "memory")
#define TCGEN05_FENCE_BEFORE() asm volatile("tcgen05.fence::before_thread_sync;" ::: "memory")
#define TCGEN05_WAIT_LD() asm volatile("tcgen05.wait::ld.sync.aligned;" ::: "memory")

#define TCGEN05_LD_32X32B_X32(r, ta)                                            \
    asm volatile("tcgen05.ld.sync.aligned.32x32b.x32.b32 "                      \
        "{%0, %1, %2, %3, %4, %5, %6, %7, %8, %9, %10, %11, %12, %13, %14, %15,"\
        " %16, %17, %18, %19, %20, %21, %22, %23, %24, %25, %26, %27, %28, %29, %30, %31}, [%32];" \
        : "=r"((r)[0]),  "=r"((r)[1]),  "=r"((r)[2]),  "=r"((r)[3]),            \
          "=r"((r)[4]),  "=r"((r)[5]),  "=r"((r)[6]),  "=r"((r)[7]),            \
          "=r"((r)[8]),  "=r"((r)[9]),  "=r"((r)[10]), "=r"((r)[11]),           \
          "=r"((r)[12]), "=r"((r)[13]), "=r"((r)[14]), "=r"((r)[15]),           \
          "=r"((r)[16]), "=r"((r)[17]), "=r"((r)[18]), "=r"((r)[19]),           \
          "=r"((r)[20]), "=r"((r)[21]), "=r"((r)[22]), "=r"((r)[23]),           \
          "=r"((r)[24]), "=r"((r)[25]), "=r"((r)[26]), "=r"((r)[27]),           \
          "=r"((r)[28]), "=r"((r)[29]), "=r"((r)[30]), "=r"((r)[31])            \
        : "r"(ta))

// idesc: kind::f16, dtype F32, atype/btype BF16, N=256, M=128 (per dispatch)
static constexpr uint32_t GEMM_IDESC =
    (1u << 4) | (1u << 7) | (1u << 10) | ((256u / 8) << 17) | ((128u / 16) << 24);

__device__ __forceinline__ void mma_f16_ss(uint32_t d, uint64_t a, uint64_t b,
                                           uint32_t idesc, bool acc) {
    uint32_t en = acc ? 1u : 0u;
    asm volatile("{\n\t.reg .pred p;\n\tsetp.ne.u32 p, %5, 0;\n\t"
                 "tcgen05.mma.cta_group::1.kind::f16 [%0], %1, %2, %3, {%4, %4, %4, %4}, p;\n\t}"
                 :: "r"(d), "l"(a), "l"(b), "r"(idesc), "r"(0u), "r"(en) : "memory");
}
#endif  // HAS_TCGEN05

// split helpers
__device__ __forceinline__ void split_bf(float v, unsigned short& h, unsigned short& l) {
    __nv_bfloat16 bh = __float2bfloat16_rn(v);
    __nv_bfloat16 bl = __float2bfloat16_rn(v - __bfloat162float(bh));
    h = __bfloat16_as_ushort(bh);
    l = __bfloat16_as_ushort(bl);
}

#define SFP 257   // smem epilogue row stride in floats (257 % 32 == 1: conflict-free)

// ---------------------------------------------------------------------------
// GEMM template. MT: 1 -> 128x256 tile, 2 -> 256x256. EPI epilogue mode:
//  0: plain fp32 C
//  1: fp32 C + A-split(t)      -> aux (hi|lo|hi)
//  2: fp32 C + Bt-split(-t)    -> aux (hi|hi|lo)      [for antisymmetric U]
//  3: t += B1 poly (-I/6 + S/24 - S2/120); A-split only -> aux
//  4: t += A0 poly ( I   - S   + S2/2  ); Bt-split only -> aux  [W = exp(-S)]
// Epilogue is smem-staged: TMEM->regs->smem (lane=row, conflict-free), then
// warp-per-row coalesced global writes (the R15 direct path wrote 8-16B per
// lane at 12KB row stride -> 4x sector amplification, +23us/launch).
// ---------------------------------------------------------------------------
template<int MT>
__device__ __forceinline__ void load_tile(uint32_t stA, uint32_t stB,
                                          const __nv_bfloat16* A, const __nv_bfloat16* Bt,
                                          size_t rowA0, size_t rowB0, int chunk, int tid) {
    const char* gA = (const char*)(A  + rowA0 * K3 + (size_t)chunk * 64);
    const char* gB = (const char*)(Bt + rowB0 * K3 + (size_t)chunk * 64);
#pragma unroll
    for (int i = 0; i < MT * 4; i++) {
        int u = tid + i * 256;
        int row = u >> 3;
        int o16 = (u & 7) << 4;
        CP_ASYNC16(stA + SMEM_SWIZZLE_128B((uint32_t)(row * 128 + o16)),
                   gA + (size_t)row * (K3 * 2) + o16);
    }
#pragma unroll
    for (int i = 0; i < 8; i++) {
        int u = tid + i * 256;
        int row = u >> 3;
        int o16 = (u & 7) << 4;
        CP_ASYNC16(stB + SMEM_SWIZZLE_128B((uint32_t)(row * 128 + o16)),
                   gB + (size_t)row * (K3 * 2) + o16);
    }
}

// coalesced write of one staged 128-row x 256-col half: warp w owns rows
// w*16..w*16+15; lanes cover 2 consecutive cols -> float2/uint32 stores.
template<int EPI>
__device__ __forceinline__ void write_half(const float* sf, size_t growbase, size_t rowB0,
                                           float* C, __nv_bfloat16* aux,
                                           const float* PS, const float* PS2,
                                           int wid, int lid) {
#pragma unroll 1
    for (int rr = 0; rr < 16; rr++) {
        int rloc = wid * 16 + rr;
        size_t grow = growbase + rloc;
#pragma unroll
        for (int j = 0; j < 4; j++) {
            int col = lid * 2 + j * 64;
            float v0 = sf[rloc * SFP + col];
            float v1 = sf[rloc * SFP + col + 1];
            int gc = (int)rowB0 + col;
            if (EPI == 3 || EPI == 4) {
                float2 s2v = *reinterpret_cast<const float2*>(PS2 + grow * NDIM + gc);
                float2 sv  = *reinterpret_cast<const float2*>(PS  + grow * NDIM + gc);
                if (EPI == 3) {
                    v0 += sv.x * (1.0f/24.0f) - s2v.x * (1.0f/120.0f)
                          - ((grow == (size_t)gc)     ? (1.0f/6.0f) : 0.0f);
                    v1 += sv.y * (1.0f/24.0f) - s2v.y * (1.0f/120.0f)
                          - ((grow == (size_t)gc + 1) ? (1.0f/6.0f) : 0.0f);
                } else {
                    v0 += -sv.x + s2v.x * 0.5f + ((grow == (size_t)gc)     ? 1.0f : 0.0f);
                    v1 += -sv.y + s2v.y * 0.5f + ((grow == (size_t)gc + 1) ? 1.0f : 0.0f);
                }
            }
            if (EPI == 0 || EPI == 1 || EPI == 2)
                *reinterpret_cast<float2*>(C + grow * NDIM + gc) = make_float2(v0, v1);
            if (EPI != 0) {
                unsigned short h0, l0, h1, l1;
                float w0 = (EPI == 2) ? -v0 : v0;
                float w1 = (EPI == 2) ? -v1 : v1;
                split_bf(w0, h0, l0);
                split_bf(w1, h1, l1);
                uint32_t hp = (uint32_t)h0 | ((uint32_t)h1 << 16);
                uint32_t lp = (uint32_t)l0 | ((uint32_t)l1 << 16);
                uint32_t* base = reinterpret_cast<uint32_t*>(aux + grow * K3 + gc);
                if (EPI == 1 || EPI == 3) {   // A-split: hi | lo | hi
                    base[0] = hp;
                    base[NDIM / 2] = lp;
                    base[NDIM] = hp;
                } else {                       // Bt-split: hi | hi | lo
                    base[0] = hp;
                    base[NDIM / 2] = hp;
                    base[NDIM] = lp;
                }
            }
        }
    }
}

template<int MT, int EPI>
__global__ __launch_bounds__(256, 1)
void gemm_bf16_kernel(const __nv_bfloat16* __restrict__ A,
                      const __nv_bfloat16* __restrict__ Bt,
                      float* __restrict__ C,
                      __nv_bfloat16* __restrict__ aux,
                      const float* __restrict__ PS,
                      const float* __restrict__ PS2) {
#if HAS_TCGEN05
    constexpr int NST = (MT == 1) ? 4 : 3;
    constexpr int A_BYTES = MT * 16384;
    constexpr int STG_BYTES = A_BYTES + 32768;
    extern __shared__ char dyn[];
    __shared__ uint64_t s_mbar[5];
    __shared__ uint32_t s_tmemptr;

    const int tid = threadIdx.x;
    const int wid = tid >> 5;
    const int lid = tid & 31;
    uint32_t sb = (smem_to_u32(dyn) + 1023) & ~1023u;
    uint32_t mb = smem_to_u32(s_mbar);

    if (tid == 0) {
        for (int i = 0; i < 5; i++) MBARRIER_INIT(mb + i * 8, 1);
    }
    if (wid == 0) {
        TCGEN05_ALLOC(smem_to_u32(&s_tmemptr), 512);
        TCGEN05_RELINQ();
    }
    __syncthreads();
    uint32_t tbase = s_tmemptr;

    const size_t rowA0 = (size_t)blockIdx.y * (MT * 128);
    const size_t rowB0 = (size_t)blockIdx.x * 256;

    for (int c = 0; c < NST - 1; c++) {
        load_tile<MT>(sb + c * STG_BYTES, sb + c * STG_BYTES + A_BYTES,
                      A, Bt, rowA0, rowB0, c, tid);
        CP_COMMIT();
    }

    int ph0 = 0, ph1 = 0, ph2 = 0, ph3 = 0;
    for (int c = 0; c < CHUNKS; c++) {
        int sc = c % NST;
        uint32_t stA = sb + sc * STG_BYTES;
        uint32_t stB = stA + A_BYTES;

        // tail: no newer groups exist to absorb the wait_group allowance, so
        // force full drain (R15 had a latent race here for the last NST-1 its)
        if (c >= CHUNKS - (NST - 1))
            asm volatile("cp.async.wait_group 0;" ::: "memory");
        else
            asm volatile("cp.async.wait_group %0;" :: "n"(NST - 2) : "memory");
        __syncthreads();

        if (wid == 0) {
            if (elect_one_pred()) {
                asm volatile("fence.proxy.async.shared::cta;" ::: "memory");
                uint64_t ad = MAKE_SMEM_DESC(stA);
                uint64_t bd = MAKE_SMEM_DESC(stB);
#pragma unroll
                for (int k = 0; k < 4; k++) {
                    bool acc = (c > 0) || (k > 0);
                    mma_f16_ss(tbase, ad + k * 2, bd + k * 2, GEMM_IDESC, acc);
                    if (MT == 2)
                        mma_f16_ss(tbase + 256, ad + 1024 + k * 2, bd + k * 2, GEMM_IDESC, acc);
                }
                TCGEN05_COMMIT(mb + sc * 8);
            }
        }

        int lc = c + NST - 1;
        if (lc < CHUNKS) {
            int sp = (c + NST - 1) % NST;   // == (c-1) mod NST
            if (c > 0) {
                int ph = (sp == 0) ? ph0 : (sp == 1) ? ph1 : (sp == 2) ? ph2 : ph3;
                MBARRIER_WAIT_PARITY(mb + sp * 8, ph);
                if (sp == 0) ph0 ^= 1; else if (sp == 1) ph1 ^= 1;
                else if (sp == 2) ph2 ^= 1; else ph3 ^= 1;
            }
            load_tile<MT>(sb + sp * STG_BYTES, sb + sp * STG_BYTES + A_BYTES,
                          A, Bt, rowA0, rowB0, lc, tid);
            CP_COMMIT();
        }
    }

    if (wid == 0 && elect_one_pred()) TCGEN05_COMMIT(mb + 32);
    MBARRIER_WAIT_PARITY(mb + 32, 0);
    TCGEN05_FENCE_AFTER();
    __syncthreads();   // all MMAs done; smem stages are now free for staging

    float* sf = reinterpret_cast<float*>(dyn);   // 128 x SFP floats = 131.6 KB

    if (MT == 1) {
        // phase 1: stage. warp w: col half (w>>2), rows (w&3)*32+lid
        {
            const int colh = wid >> 2;
            const int sub  = wid & 3;
            int rloc = sub * 32 + lid;
#pragma unroll 1
            for (int j = 0; j < 4; j++) {
                uint32_t r[32];
                TCGEN05_LD_32X32B_X32(r, tbase + colh * 128 + j * 32);
                TCGEN05_WAIT_LD();
#pragma unroll
                for (int k = 0; k < 32; k++)
                    sf[rloc * SFP + colh * 128 + j * 32 + k] = __uint_as_float(r[k]);
            }
        }
        __syncthreads();
        // phase 2: coalesced writes
        write_half<EPI>(sf, rowA0, rowB0, C, aux, PS, PS2, wid, lid);
    } else {
        // two 128-row halves
#pragma unroll 1
        for (int half = 0; half < 2; half++) {
            if ((wid >> 2) == half) {
                int rloc = (wid & 3) * 32 + lid;
#pragma unroll 1
                for (int j = 0; j < 8; j++) {
                    uint32_t r[32];
                    TCGEN05_LD_32X32B_X32(r, tbase + half * 256 + j * 32);
                    TCGEN05_WAIT_LD();
#pragma unroll
                    for (int k = 0; k < 32; k++)
                        sf[rloc * SFP + j * 32 + k] = __uint_as_float(r[k]);
                }
            }
            __syncthreads();
            write_half<0>(sf, rowA0 + half * 128, rowB0, C, aux, PS, PS2, wid, lid);
            __syncthreads();
        }
    }
    TCGEN05_FENCE_BEFORE();
    __syncthreads();
    if (wid == 0) TCGEN05_DEALLOC(tbase, 512);
#endif  // HAS_TCGEN05
}

// ---------------------------------------------------------------------------
// elementwise kernels (3 total)
// ---------------------------------------------------------------------------
__global__ void build_S_fused(const float* __restrict__ flat, float* __restrict__ S,
                              __nv_bfloat16* __restrict__ ASp, __nv_bfloat16* __restrict__ BtN) {
    int idx = blockIdx.x * blockDim.x + threadIdx.x;
    int r = idx >> 11, c = idx & 2047;
    float v = 0.0f;
    if (r < c) {
        int off = r * (NDIM - 1) - (r * (r - 1)) / 2;
        v = flat[off + (c - r - 1)];
    } else if (r > c) {
        int off = c * (NDIM - 1) - (c * (c - 1)) / 2;
        v = -flat[off + (r - c - 1)];
    }
    S[idx] = v;
    unsigned short h, l, nh, nl;
    split_bf(v, h, l);
    split_bf(-v, nh, nl);
    size_t b = (size_t)r * K3 + c;
    ASp[b] = __ushort_as_bfloat16(h);
    ASp[b + NDIM] = __ushort_as_bfloat16(l);
    ASp[b + 2 * NDIM] = __ushort_as_bfloat16(h);
    BtN[b] = __ushort_as_bfloat16(nh);
    BtN[b + NDIM] = __ushort_as_bfloat16(nh);
    BtN[b + 2 * NDIM] = __ushort_as_bfloat16(nl);
}

__global__ void b2split_kernel(const float* __restrict__ S, const float* __restrict__ S2,
                               const float* __restrict__ U, __nv_bfloat16* __restrict__ ASp) {
    int idx = blockIdx.x * blockDim.x + threadIdx.x;   // over NN/4
    int flat = idx * 4;
    int r = flat >> 11;
    float4 s  = *(const float4*)(S  + flat);
    float4 s2 = *(const float4*)(S2 + flat);
    float4 u  = *(const float4*)(U  + flat);
    const float* sp  = &s.x;
    const float* sp2 = &s2.x;
    const float* up  = &u.x;
    unsigned short h[4], l[4];
#pragma unroll
    for (int i = 0; i < 4; i++) {
        float v = -sp[i] * (1.0f/5040.0f) + sp2[i] * (1.0f/40320.0f) - up[i] * (1.0f/362880.0f);
        if (r == ((flat + i) & 2047)) v += 1.0f/720.0f;
        split_bf(v, h[i], l[i]);
    }
    uint2 hp = make_uint2((uint32_t)h[0] | ((uint32_t)h[1] << 16),
                          (uint32_t)h[2] | ((uint32_t)h[3] << 16));
    uint2 lp = make_uint2((uint32_t)l[0] | ((uint32_t)l[1] << 16),
                          (uint32_t)l[2] | ((uint32_t)l[3] << 16));
    __nv_bfloat16* base = ASp + (size_t)r * K3 + (flat & 2047);
    *reinterpret_cast<uint2*>(base) = hp;
    *reinterpret_cast<uint2*>(base + NDIM) = lp;
    *reinterpret_cast<uint2*>(base + 2 * NDIM) = hp;
}

__global__ void splitAX_kernel(const float* __restrict__ in, __nv_bfloat16* __restrict__ out) {
    int idx = blockIdx.x * blockDim.x + threadIdx.x;   // over BATCH*NDIM/4
    int flat4 = idx * 4;
    int r = flat4 >> 11;
    int c = flat4 & 2047;
    float4 x = *(const float4*)(in + (size_t)flat4);
    const float* xp = &x.x;
    unsigned short h[4], l[4];
#pragma unroll
    for (int i = 0; i < 4; i++) split_bf(xp[i], h[i], l[i]);
    uint2 hp = make_uint2((uint32_t)h[0] | ((uint32_t)h[1] << 16),
                          (uint32_t)h[2] | ((uint32_t)h[3] << 16));
    uint2 lp = make_uint2((uint32_t)l[0] | ((uint32_t)l[1] << 16),
                          (uint32_t)l[2] | ((uint32_t)l[3] << 16));
    __nv_bfloat16* base = out + (size_t)r * K3 + c;
    *reinterpret_cast<uint2*>(base) = hp;
    *reinterpret_cast<uint2*>(base + NDIM) = lp;
    *reinterpret_cast<uint2*>(base + 2 * NDIM) = hp;
}

// ---------------------------------------------------------------------------
// W = exp(-S) = A0 + (B1 + B2*U)*U   (U = S^3)
// A0 = I - S + S2/2 ; B1 = -I/6 + S/24 - S2/120
// B2 = I/720 - S/5040 + S2/40320 - U/362880
// Y = X @ exp(S); Bt(exp(S)) = W row-major (no transposes anywhere).
// ---------------------------------------------------------------------------
extern "C" void kernel_launch(void* const* d_in, const int* in_sizes, int n_in,
                              void* d_out, int out_size) {
    const float* X    = (const float*)d_in[0];
    const float* flat = (const float*)d_in[1];
    float*       Y    = (float*)d_out;

    float *S, *S2, *U;
    __nv_bfloat16 *A1, *A2, *SBtN, *UBtN, *WBt, *XA;
    cudaGetSymbolAddress((void**)&S,  g_S);
    cudaGetSymbolAddress((void**)&S2, g_S2);
    cudaGetSymbolAddress((void**)&U,  g_U);
    cudaGetSymbolAddress((void**)&A1, g_A1);
    cudaGetSymbolAddress((void**)&A2, g_A2);
    cudaGetSymbolAddress((void**)&SBtN, g_SBtN);
    cudaGetSymbolAddress((void**)&UBtN, g_UBtN);
    cudaGetSymbolAddress((void**)&WBt,  g_WBt);
    cudaGetSymbolAddress((void**)&XA,   g_XA);

    const int SMEM1 = 4 * (16384 + 32768) + 1024;   // 197632
    const int SMEM2 = 3 * (32768 + 32768) + 1024;   // 197632
    cudaFuncSetAttribute(gemm_bf16_kernel<1,1>, cudaFuncAttributeMaxDynamicSharedMemorySize, SMEM1);
    cudaFuncSetAttribute(gemm_bf16_kernel<1,2>, cudaFuncAttributeMaxDynamicSharedMemorySize, SMEM1);
    cudaFuncSetAttribute(gemm_bf16_kernel<1,3>, cudaFuncAttributeMaxDynamicSharedMemorySize, SMEM1);
    cudaFuncSetAttribute(gemm_bf16_kernel<1,4>, cudaFuncAttributeMaxDynamicSharedMemorySize, SMEM1);
    cudaFuncSetAttribute(gemm_bf16_kernel<2,0>, cudaFuncAttributeMaxDynamicSharedMemorySize, SMEM2);

    const int NN = NDIM * NDIM;
    dim3 blk256(256);
    dim3 gNN(NDIM / 256, NDIM / 128);    // MT=1: 128 CTAs
    dim3 gY (NDIM / 256, BATCH / 256);   // MT=2: 256 CTAs

    // 1. S, A-split(S) -> A1, Bt-split(-S) -> SBtN
    build_S_fused<<<NN / 256, blk256>>>(flat, S, A1, SBtN);

    // X -> XA (independent; schedule early)
    splitAX_kernel<<<(BATCH * NDIM) / 1024, blk256>>>(X, XA);

    // 2. S2 = S@S ; epi: fp32 S2 + A-split(S2) -> A2
    gemm_bf16_kernel<1,1><<<gNN, blk256, SMEM1>>>(A1, SBtN, S2, A2, nullptr, nullptr);

    // 3. U = S2@S ; epi: fp32 U + Bt-split(-U) -> UBtN
    gemm_bf16_kernel<1,2><<<gNN, blk256, SMEM1>>>(A2, SBtN, U, UBtN, nullptr, nullptr);

    // 4. A-split(B2) -> A1
    b2split_kernel<<<NN / 1024, blk256>>>(S, S2, U, A1);

    // 5. T1 = B2@U ; epi: M1 = B1 + T1, A-split(M1) -> A2
    gemm_bf16_kernel<1,3><<<gNN, blk256, SMEM1>>>(A1, UBtN, nullptr, A2, S, S2);

    // 6. T0 = M1@U ; epi: W = A0 + T0, Bt-split(W) -> WBt
    gemm_bf16_kernel<1,4><<<gNN, blk256, SMEM1>>>(A2, UBtN, nullptr, WBt, S, S2);

    // 7. Y = XA @ WBt
    gemm_bf16_kernel<2,0><<<gY, blk256, SMEM2>>>(XA, WBt, Y, nullptr, nullptr, nullptr);
}